// round 6
// baseline (speedup 1.0000x reference)
#include <cuda_runtime.h>
#include <cuda_bf16.h>
#include <cstdint>

// ---------------------------------------------------------------------------
// LIF layer forward (sm_103 base ISA):
//   cur = x @ W^T + bias   (3-pass split-bf16 HMMA GEMM, ldmatrix feeds)
//   scan: v = d*v*(1-z) + (1-d)*(cur_t + z @ R^T);  z = (v >= 1)
// d_out = [outputs | statesV | statesZ]
// ---------------------------------------------------------------------------

#define IN_DIM  512
#define OUT_DIM 512
#define MAX_M   64000

__device__ __nv_bfloat16 g_xhi[(size_t)MAX_M * IN_DIM];
__device__ __nv_bfloat16 g_xlo[(size_t)MAX_M * IN_DIM];
__device__ __nv_bfloat16 g_whi[(size_t)OUT_DIM * IN_DIM];
__device__ __nv_bfloat16 g_wlo[(size_t)OUT_DIM * IN_DIM];
__device__ float         g_RT [(size_t)OUT_DIM * OUT_DIM];

// ======================= conversion kernels =================================
__global__ void convert_x_kernel(const float* __restrict__ x, long long n4) {
    long long i = (long long)blockIdx.x * blockDim.x + threadIdx.x;
    if (i >= n4) return;
    float4 v = ((const float4*)x)[i];
    float vv[4] = {v.x, v.y, v.z, v.w};
    __nv_bfloat16 h[4], l[4];
#pragma unroll
    for (int k = 0; k < 4; k++) {
        h[k] = __float2bfloat16_rn(vv[k]);
        l[k] = __float2bfloat16_rn(vv[k] - __bfloat162float(h[k]));
    }
    __nv_bfloat162* hi2 = (__nv_bfloat162*)g_xhi;
    __nv_bfloat162* lo2 = (__nv_bfloat162*)g_xlo;
    hi2[i * 2]     = __halves2bfloat162(h[0], h[1]);
    hi2[i * 2 + 1] = __halves2bfloat162(h[2], h[3]);
    lo2[i * 2]     = __halves2bfloat162(l[0], l[1]);
    lo2[i * 2 + 1] = __halves2bfloat162(l[2], l[3]);
}

__global__ void convert_w_kernel(const float* __restrict__ w) {
    int i = blockIdx.x * blockDim.x + threadIdx.x;
    float4 v = ((const float4*)w)[i];
    float vv[4] = {v.x, v.y, v.z, v.w};
    __nv_bfloat16 h[4], l[4];
#pragma unroll
    for (int k = 0; k < 4; k++) {
        h[k] = __float2bfloat16_rn(vv[k]);
        l[k] = __float2bfloat16_rn(vv[k] - __bfloat162float(h[k]));
    }
    __nv_bfloat162* hi2 = (__nv_bfloat162*)g_whi;
    __nv_bfloat162* lo2 = (__nv_bfloat162*)g_wlo;
    hi2[i * 2]     = __halves2bfloat162(h[0], h[1]);
    hi2[i * 2 + 1] = __halves2bfloat162(h[2], h[3]);
    lo2[i * 2]     = __halves2bfloat162(l[0], l[1]);
    lo2[i * 2 + 1] = __halves2bfloat162(l[2], l[3]);
}

__global__ void transpose512_kernel(const float* __restrict__ R) {
    __shared__ float tile[32][33];
    int x = blockIdx.x * 32 + threadIdx.x;
    int y = blockIdx.y * 32 + threadIdx.y;
    tile[threadIdx.y][threadIdx.x] = R[y * OUT_DIM + x];
    __syncthreads();
    int xo = blockIdx.y * 32 + threadIdx.x;
    int yo = blockIdx.x * 32 + threadIdx.y;
    g_RT[yo * OUT_DIM + xo] = tile[threadIdx.x][threadIdx.y];
}

// ======================= HMMA GEMM ==========================================
// CTA 128x128, BK=64 (8 stages), double-buffered cp.async.
// Warp grid 4(m) x 2(n); warp tile 32x64; ldmatrix.x4 fragment loads.
// SMEM rows stride 72 bf16 = 144 B (=128+16 -> 8 consecutive rows hit 8
// distinct 16B bank slots: ldmatrix conflict-free).
#define TSTRIDE   72
#define ROW_B     (TSTRIDE * 2)                 // 144
#define PART_B    (128 * ROW_B)                 // 18432
#define STAGE_B   (4 * PART_B)                  // 73728
#define SMEM_GEMM (2 * STAGE_B)                 // 147456

__device__ __forceinline__ uint32_t smem_u32(const void* p) {
    uint32_t a;
    asm("{ .reg .u64 t; cvta.to.shared.u64 t, %1; cvt.u32.u64 %0, t; }"
        : "=r"(a) : "l"(p));
    return a;
}

__device__ __forceinline__ void cp16(uint32_t dst, const void* src) {
    asm volatile("cp.async.cg.shared.global [%0], [%1], 16;" :: "r"(dst), "l"(src));
}

__device__ __forceinline__ void ldsm_x4(uint32_t* r, uint32_t addr) {
    asm volatile("ldmatrix.sync.aligned.m8n8.x4.shared.b16 {%0,%1,%2,%3}, [%4];"
        : "=r"(r[0]), "=r"(r[1]), "=r"(r[2]), "=r"(r[3]) : "r"(addr));
}

__device__ __forceinline__ void mma_bf16(float* d, const uint32_t* a,
                                         uint32_t b0, uint32_t b1) {
    asm volatile(
        "mma.sync.aligned.m16n8k16.row.col.f32.bf16.bf16.f32 "
        "{%0,%1,%2,%3}, {%4,%5,%6,%7}, {%8,%9}, {%0,%1,%2,%3};"
        : "+f"(d[0]), "+f"(d[1]), "+f"(d[2]), "+f"(d[3])
        : "r"(a[0]), "r"(a[1]), "r"(a[2]), "r"(a[3]), "r"(b0), "r"(b1));
}

__device__ __forceinline__ void load_stage(uint32_t sbase, int buf,
        const __nv_bfloat16* Ah, const __nv_bfloat16* Al,
        const __nv_bfloat16* Bh, const __nv_bfloat16* Bl,
        int k0, int tid) {
    uint32_t base = sbase + buf * STAGE_B;
    const __nv_bfloat16* srcs[4] = {Ah, Al, Bh, Bl};
#pragma unroll
    for (int p = 0; p < 4; p++) {
        uint32_t pb = base + p * PART_B;
        const __nv_bfloat16* gp = srcs[p] + k0;
#pragma unroll
        for (int it = 0; it < 4; it++) {
            int chunk = it * 256 + tid;         // 1024 chunks: 128 rows x 8x16B
            int row = chunk >> 3;
            int cc  = chunk & 7;
            cp16(pb + row * ROW_B + cc * 16,
                 gp + (size_t)row * IN_DIM + cc * 8);
        }
    }
    asm volatile("cp.async.commit_group;");
}

__global__ __launch_bounds__(256)
void gemm_hmma_kernel(const float* __restrict__ bias, float* __restrict__ C) {
    extern __shared__ char sm[];
    const uint32_t sbase = smem_u32(sm);
    const int tid  = threadIdx.x;
    const int wid  = tid >> 5;
    const int lane = tid & 31;
    const int g = lane >> 2, t = lane & 3;
    const int wm = wid >> 1;                    // m offset wm*32
    const int wn = wid & 1;                     // n offset wn*64
    // n varies fastest across CTA ids -> A rows reused by 4 consecutive CTAs
    const int n0 = blockIdx.x * 128;
    const int m0 = blockIdx.y * 128;

    const __nv_bfloat16* Ah = g_xhi + (size_t)m0 * IN_DIM;
    const __nv_bfloat16* Al = g_xlo + (size_t)m0 * IN_DIM;
    const __nv_bfloat16* Bh = g_whi + (size_t)n0 * IN_DIM;
    const __nv_bfloat16* Bl = g_wlo + (size_t)n0 * IN_DIM;

    // ldmatrix lane byte offsets within a part
    const uint32_t aRowOff = (uint32_t)(wm * 32 + (lane & 15)) * ROW_B + (lane >> 4) * 16;
    const uint32_t bRowOff = (uint32_t)(wn * 64 + (lane & 15)) * ROW_B + (lane >> 4) * 16;

    float d[2][8][4];
#pragma unroll
    for (int mi = 0; mi < 2; mi++)
#pragma unroll
        for (int nj = 0; nj < 8; nj++)
#pragma unroll
            for (int r = 0; r < 4; r++) d[mi][nj][r] = 0.f;

    load_stage(sbase, 0, Ah, Al, Bh, Bl, 0, tid);

#pragma unroll 1
    for (int s = 0; s < 8; s++) {
        if (s < 7) {
            load_stage(sbase, (s + 1) & 1, Ah, Al, Bh, Bl, (s + 1) * 64, tid);
            asm volatile("cp.async.wait_group 1;");
        } else {
            asm volatile("cp.async.wait_group 0;");
        }
        __syncthreads();

        const uint32_t stg = sbase + (s & 1) * STAGE_B;
        const uint32_t aHb = stg              + aRowOff;
        const uint32_t aLb = stg + PART_B     + aRowOff;
        const uint32_t bHb = stg + 2 * PART_B + bRowOff;
        const uint32_t bLb = stg + 3 * PART_B + bRowOff;

#pragma unroll
        for (int kk = 0; kk < 4; kk++) {
            const uint32_t ko = kk * 32;        // 16 bf16 = 32 bytes
            uint32_t aH[2][4], aL[2][4], bH[4][4], bL[4][4];
#pragma unroll
            for (int mi = 0; mi < 2; mi++) {
                ldsm_x4(aH[mi], aHb + mi * (16 * ROW_B) + ko);
                ldsm_x4(aL[mi], aLb + mi * (16 * ROW_B) + ko);
            }
#pragma unroll
            for (int p = 0; p < 4; p++) {
                ldsm_x4(bH[p], bHb + p * (16 * ROW_B) + ko);
                ldsm_x4(bL[p], bLb + p * (16 * ROW_B) + ko);
            }
#pragma unroll
            for (int mi = 0; mi < 2; mi++)
#pragma unroll
                for (int p = 0; p < 4; p++) {
                    // nj = 2p   : rows p*16+0..7  -> regs {0,2}
                    // nj = 2p+1 : rows p*16+8..15 -> regs {1,3}
                    mma_bf16(d[mi][2 * p],     aH[mi], bH[p][0], bH[p][2]);
                    mma_bf16(d[mi][2 * p],     aH[mi], bL[p][0], bL[p][2]);
                    mma_bf16(d[mi][2 * p],     aL[mi], bH[p][0], bH[p][2]);
                    mma_bf16(d[mi][2 * p + 1], aH[mi], bH[p][1], bH[p][3]);
                    mma_bf16(d[mi][2 * p + 1], aH[mi], bL[p][1], bL[p][3]);
                    mma_bf16(d[mi][2 * p + 1], aL[mi], bH[p][1], bH[p][3]);
                }
        }
        __syncthreads();
    }

    // Epilogue: direct float2 stores + bias
#pragma unroll
    for (int nj = 0; nj < 8; nj++) {
        int cc = n0 + wn * 64 + nj * 8 + 2 * t;
        float2 bv = *(const float2*)&bias[cc];
#pragma unroll
        for (int mi = 0; mi < 2; mi++) {
            int r0 = m0 + wm * 32 + mi * 16 + g;
            float2 o0 = {d[mi][nj][0] + bv.x, d[mi][nj][1] + bv.y};
            float2 o1 = {d[mi][nj][2] + bv.x, d[mi][nj][3] + bv.y};
            *(float2*)&C[(size_t)r0 * OUT_DIM + cc]       = o0;
            *(float2*)&C[(size_t)(r0 + 8) * OUT_DIM + cc] = o1;
        }
    }
}

// ======================= LIF sequential scan ================================
// 128 threads x 4 neurons each (float4 path, 4-warp barrier).
__device__ __forceinline__ void step4(
    float4 c, float4& v, float4& z, int& anySpike,
    unsigned* smask, int o4, int wid, int lane,
    float4 dd, float4 omd,
    float4* __restrict__ outP, float4* __restrict__ svP, float4* __restrict__ szP)
{
    float s0 = c.x, s1 = c.y, s2 = c.z, s3 = c.w;
    if (anySpike) {
#pragma unroll 1
        for (int w = 0; w < 16; w++) {
            unsigned m = smask[w];
            while (m) {
                int j = w * 32 + (__ffs(m) - 1);
                m &= (m - 1);
                const float4 r = *(const float4*)&g_RT[(size_t)j * OUT_DIM + o4];
                s0 += r.x; s1 += r.y; s2 += r.z; s3 += r.w;
            }
        }
    }
    v.x = dd.x * (v.x * (1.f - z.x)) + omd.x * s0;
    v.y = dd.y * (v.y * (1.f - z.y)) + omd.y * s1;
    v.z = dd.z * (v.z * (1.f - z.z)) + omd.z * s2;
    v.w = dd.w * (v.w * (1.f - z.w)) + omd.w * s3;
    z.x = (v.x >= 1.f) ? 1.f : 0.f;
    z.y = (v.y >= 1.f) ? 1.f : 0.f;
    z.z = (v.z >= 1.f) ? 1.f : 0.f;
    z.w = (v.w >= 1.f) ? 1.f : 0.f;
    *outP = z;  *svP = v;  *szP = z;
    bool sp = (z.x + z.y + z.z + z.w) > 0.f;
    anySpike = __syncthreads_count(sp);        // barrier: mask reads above / writes below
    if (anySpike) {                            // block-uniform (count)
        unsigned nib = (z.x > 0.f ? 1u : 0u) | (z.y > 0.f ? 2u : 0u) |
                       (z.z > 0.f ? 4u : 0u) | (z.w > 0.f ? 8u : 0u);
        unsigned word = 0;
#pragma unroll
        for (int l = 0; l < 8; l++) {
            unsigned nl = __shfl_sync(0xffffffffu, nib, ((lane & 3) << 3) + l);
            word |= nl << (4 * l);
        }
        if (lane < 4) smask[wid * 4 + lane] = word;
        __syncthreads();
    }
}

__global__ __launch_bounds__(128, 1)
void scan_kernel(const float* __restrict__ cur,
                 const float* __restrict__ decay,
                 float* __restrict__ outputs,
                 float* __restrict__ statesV,
                 float* __restrict__ statesZ,
                 int T) {
    const int b = blockIdx.x;
    const int tid = threadIdx.x;
    const int o4 = tid * 4;
    const int wid = tid >> 5, lane = tid & 31;

    __shared__ unsigned smask[16];
    if (tid < 16) smask[tid] = 0u;

    float4 dd  = *(const float4*)&decay[o4];
    float4 omd = {1.f - dd.x, 1.f - dd.y, 1.f - dd.z, 1.f - dd.w};

    const float* curB = cur     + (size_t)b * T * OUT_DIM;
    float* outB = outputs + (size_t)b * T * OUT_DIM;
    float* svB  = statesV + (size_t)b * (T + 1) * OUT_DIM;
    float* szB  = statesZ + (size_t)b * (T + 1) * OUT_DIM;

    const float4 zero4 = {0.f, 0.f, 0.f, 0.f};
    *(float4*)&svB[o4] = zero4;
    *(float4*)&szB[o4] = zero4;

    float4 v = zero4, z = zero4;
    int anySpike = 0;
    __syncthreads();

    // 8-deep prefetch ring (MLP=8 hides DRAM latency across the barrier chain)
    float4 c[8];
#pragma unroll
    for (int i = 0; i < 8; i++)
        c[i] = (i < T) ? *(const float4*)&curB[(size_t)i * OUT_DIM + o4] : zero4;

    int t = 0;
#pragma unroll 1
    for (; t + 8 <= T; t += 8) {
#pragma unroll
        for (int u = 0; u < 8; u++) {
            int tt = t + u;
            float4 cn = zero4;
            if (tt + 8 < T) cn = *(const float4*)&curB[(size_t)(tt + 8) * OUT_DIM + o4];
            step4(c[u], v, z, anySpike, smask, o4, wid, lane, dd, omd,
                  (float4*)&outB[(size_t)tt * OUT_DIM + o4],
                  (float4*)&svB[(size_t)(tt + 1) * OUT_DIM + o4],
                  (float4*)&szB[(size_t)(tt + 1) * OUT_DIM + o4]);
            c[u] = cn;
        }
    }
#pragma unroll 1
    for (int u = 0; t < T; t++, u++) {
        step4(c[u], v, z, anySpike, smask, o4, wid, lane, dd, omd,
              (float4*)&outB[(size_t)t * OUT_DIM + o4],
              (float4*)&svB[(size_t)(t + 1) * OUT_DIM + o4],
              (float4*)&szB[(size_t)(t + 1) * OUT_DIM + o4]);
    }
}

// ---------------------------------------------------------------------------
extern "C" void kernel_launch(void* const* d_in, const int* in_sizes, int n_in,
                              void* d_out, int out_size) {
    const float* x      = (const float*)d_in[0];  // [B, T, IN]
    const float* weight = (const float*)d_in[1];  // [OUT, IN]
    const float* bias   = (const float*)d_in[2];  // [OUT]
    const float* recur  = (const float*)d_in[3];  // [OUT, OUT]
    const float* decay  = (const float*)d_in[4];  // [OUT]

    const int OUT = in_sizes[2];                         // 512
    const int IN  = in_sizes[1] / OUT;                   // 512
    const long long M = (long long)in_sizes[0] / IN;     // B*T
    const long long B = (((long long)out_size / OUT) - 3 * M) / 2;
    const int T = (int)(M / B);

    float* outputs = (float*)d_out;                        // [B,T,OUT]
    float* statesV = outputs + (size_t)B * T * OUT;        // [B,T+1,OUT]
    float* statesZ = statesV + (size_t)B * (T + 1) * OUT;  // [B,T+1,OUT]
    // cur aliases outputs: cur[b,t,o] is read (<=8 steps early) strictly before
    // outputs[b,t,o] is written by the same thread; indices coincide 1:1.
    float* cur = outputs;

    long long n4x = M * IN / 4;
    convert_x_kernel<<<(unsigned)((n4x + 255) / 256), 256>>>(x, n4x);
    convert_w_kernel<<<(OUT * IN / 4) / 256, 256>>>(weight);

    {
        dim3 grid(OUT / 32, OUT / 32), block(32, 32);
        transpose512_kernel<<<grid, block>>>(recur);
    }

    cudaFuncSetAttribute(gemm_hmma_kernel,
                         cudaFuncAttributeMaxDynamicSharedMemorySize, SMEM_GEMM);
    {
        dim3 grid(OUT / 128, (unsigned)(M / 128));   // n fastest -> A reuse in L2
        gemm_hmma_kernel<<<grid, 256, SMEM_GEMM>>>(bias, cur);
    }

    scan_kernel<<<(unsigned)B, 128>>>(cur, decay, outputs, statesV, statesZ, T);
}

// round 7
// speedup vs baseline: 1.1399x; 1.1399x over previous
#include <cuda_runtime.h>
#include <cuda_bf16.h>
#include <cstdint>

// ---------------------------------------------------------------------------
// LIF layer forward (sm_103 base ISA):
//   cur = x @ W^T + bias   (3-pass split-bf16 HMMA GEMM, ldmatrix feeds)
//   scan: v = d*v*(1-z) + (1-d)*(cur_t + z @ R^T);  z = (v >= 1)
// d_out = [outputs | statesV | statesZ]
// ---------------------------------------------------------------------------

#define IN_DIM  512
#define OUT_DIM 512
#define MAX_M   64000

__device__ __nv_bfloat16 g_xhi[(size_t)MAX_M * IN_DIM];
__device__ __nv_bfloat16 g_xlo[(size_t)MAX_M * IN_DIM];
__device__ __nv_bfloat16 g_whi[(size_t)OUT_DIM * IN_DIM];
__device__ __nv_bfloat16 g_wlo[(size_t)OUT_DIM * IN_DIM];
__device__ float         g_RT [(size_t)OUT_DIM * OUT_DIM];

// ======================= conversion kernels =================================
__global__ void convert_x_kernel(const float* __restrict__ x, long long n4) {
    long long i = (long long)blockIdx.x * blockDim.x + threadIdx.x;
    if (i >= n4) return;
    float4 v = ((const float4*)x)[i];
    float vv[4] = {v.x, v.y, v.z, v.w};
    __nv_bfloat16 h[4], l[4];
#pragma unroll
    for (int k = 0; k < 4; k++) {
        h[k] = __float2bfloat16_rn(vv[k]);
        l[k] = __float2bfloat16_rn(vv[k] - __bfloat162float(h[k]));
    }
    __nv_bfloat162* hi2 = (__nv_bfloat162*)g_xhi;
    __nv_bfloat162* lo2 = (__nv_bfloat162*)g_xlo;
    hi2[i * 2]     = __halves2bfloat162(h[0], h[1]);
    hi2[i * 2 + 1] = __halves2bfloat162(h[2], h[3]);
    lo2[i * 2]     = __halves2bfloat162(l[0], l[1]);
    lo2[i * 2 + 1] = __halves2bfloat162(l[2], l[3]);
}

__global__ void convert_w_kernel(const float* __restrict__ w) {
    int i = blockIdx.x * blockDim.x + threadIdx.x;
    float4 v = ((const float4*)w)[i];
    float vv[4] = {v.x, v.y, v.z, v.w};
    __nv_bfloat16 h[4], l[4];
#pragma unroll
    for (int k = 0; k < 4; k++) {
        h[k] = __float2bfloat16_rn(vv[k]);
        l[k] = __float2bfloat16_rn(vv[k] - __bfloat162float(h[k]));
    }
    __nv_bfloat162* hi2 = (__nv_bfloat162*)g_whi;
    __nv_bfloat162* lo2 = (__nv_bfloat162*)g_wlo;
    hi2[i * 2]     = __halves2bfloat162(h[0], h[1]);
    hi2[i * 2 + 1] = __halves2bfloat162(h[2], h[3]);
    lo2[i * 2]     = __halves2bfloat162(l[0], l[1]);
    lo2[i * 2 + 1] = __halves2bfloat162(l[2], l[3]);
}

__global__ void transpose512_kernel(const float* __restrict__ R) {
    __shared__ float tile[32][33];
    int x = blockIdx.x * 32 + threadIdx.x;
    int y = blockIdx.y * 32 + threadIdx.y;
    tile[threadIdx.y][threadIdx.x] = R[y * OUT_DIM + x];
    __syncthreads();
    int xo = blockIdx.y * 32 + threadIdx.x;
    int yo = blockIdx.x * 32 + threadIdx.y;
    g_RT[yo * OUT_DIM + xo] = tile[threadIdx.x][threadIdx.y];
}

// ======================= HMMA GEMM ==========================================
// CTA 128x128, BK=32 (16 stages), double-buffered cp.async, 2 CTAs/SM.
// Warp grid 4(m) x 2(n); warp tile 32x64; ldmatrix.x4 fragment loads.
// SMEM rows: 32 bf16 = 64 B + 16 pad = 80 B stride (bank16 = 5r mod 32:
// any 8 consecutive rows hit distinct 16B banks -> ldmatrix conflict-free).
#define ROW_B     80
#define PART_B    (128 * ROW_B)                 // 10240
#define STAGE_B   (4 * PART_B)                  // 40960
#define SMEM_GEMM (2 * STAGE_B)                 // 81920 (2 CTAs/SM fit)

__device__ __forceinline__ uint32_t smem_u32(const void* p) {
    uint32_t a;
    asm("{ .reg .u64 t; cvta.to.shared.u64 t, %1; cvt.u32.u64 %0, t; }"
        : "=r"(a) : "l"(p));
    return a;
}

__device__ __forceinline__ void cp16(uint32_t dst, const void* src) {
    asm volatile("cp.async.cg.shared.global [%0], [%1], 16;" :: "r"(dst), "l"(src));
}

__device__ __forceinline__ void ldsm_x4(uint32_t* r, uint32_t addr) {
    asm volatile("ldmatrix.sync.aligned.m8n8.x4.shared.b16 {%0,%1,%2,%3}, [%4];"
        : "=r"(r[0]), "=r"(r[1]), "=r"(r[2]), "=r"(r[3]) : "r"(addr));
}

__device__ __forceinline__ void mma_bf16(float* d, const uint32_t* a,
                                         uint32_t b0, uint32_t b1) {
    asm volatile(
        "mma.sync.aligned.m16n8k16.row.col.f32.bf16.bf16.f32 "
        "{%0,%1,%2,%3}, {%4,%5,%6,%7}, {%8,%9}, {%0,%1,%2,%3};"
        : "+f"(d[0]), "+f"(d[1]), "+f"(d[2]), "+f"(d[3])
        : "r"(a[0]), "r"(a[1]), "r"(a[2]), "r"(a[3]), "r"(b0), "r"(b1));
}

__device__ __forceinline__ void load_stage(uint32_t sbase, int buf,
        const __nv_bfloat16* Ah, const __nv_bfloat16* Al,
        const __nv_bfloat16* Bh, const __nv_bfloat16* Bl,
        int k0, int tid) {
    uint32_t base = sbase + buf * STAGE_B;
    const __nv_bfloat16* srcs[4] = {Ah, Al, Bh, Bl};
#pragma unroll
    for (int p = 0; p < 4; p++) {
        uint32_t pb = base + p * PART_B;
        const __nv_bfloat16* gp = srcs[p] + k0;
#pragma unroll
        for (int it = 0; it < 2; it++) {        // 512 chunks: 128 rows x 4x16B
            int chunk = it * 256 + tid;
            int row = chunk >> 2;
            int cc  = chunk & 3;
            cp16(pb + row * ROW_B + cc * 16,
                 gp + (size_t)row * IN_DIM + cc * 8);
        }
    }
    asm volatile("cp.async.commit_group;");
}

__global__ __launch_bounds__(256, 2)
void gemm_hmma_kernel(const float* __restrict__ bias, float* __restrict__ C) {
    extern __shared__ char sm[];
    const uint32_t sbase = smem_u32(sm);
    const int tid  = threadIdx.x;
    const int wid  = tid >> 5;
    const int lane = tid & 31;
    const int g = lane >> 2, t = lane & 3;
    const int wm = wid >> 1;
    const int wn = wid & 1;
    // n varies fastest across CTA ids -> A rows reused by 4 consecutive CTAs
    const int n0 = blockIdx.x * 128;
    const int m0 = blockIdx.y * 128;

    const __nv_bfloat16* Ah = g_xhi + (size_t)m0 * IN_DIM;
    const __nv_bfloat16* Al = g_xlo + (size_t)m0 * IN_DIM;
    const __nv_bfloat16* Bh = g_whi + (size_t)n0 * IN_DIM;
    const __nv_bfloat16* Bl = g_wlo + (size_t)n0 * IN_DIM;

    const uint32_t aRowOff = (uint32_t)(wm * 32 + (lane & 15)) * ROW_B + (lane >> 4) * 16;
    const uint32_t bRowOff = (uint32_t)(wn * 64 + (lane & 15)) * ROW_B + (lane >> 4) * 16;

    float d[2][8][4];
#pragma unroll
    for (int mi = 0; mi < 2; mi++)
#pragma unroll
        for (int nj = 0; nj < 8; nj++)
#pragma unroll
            for (int r = 0; r < 4; r++) d[mi][nj][r] = 0.f;

    load_stage(sbase, 0, Ah, Al, Bh, Bl, 0, tid);

#pragma unroll 1
    for (int s = 0; s < 16; s++) {
        if (s < 15) {
            load_stage(sbase, (s + 1) & 1, Ah, Al, Bh, Bl, (s + 1) * 32, tid);
            asm volatile("cp.async.wait_group 1;");
        } else {
            asm volatile("cp.async.wait_group 0;");
        }
        __syncthreads();

        const uint32_t stg = sbase + (s & 1) * STAGE_B;
        const uint32_t aHb = stg              + aRowOff;
        const uint32_t aLb = stg + PART_B     + aRowOff;
        const uint32_t bHb = stg + 2 * PART_B + bRowOff;
        const uint32_t bLb = stg + 3 * PART_B + bRowOff;

#pragma unroll
        for (int kk = 0; kk < 2; kk++) {
            const uint32_t ko = kk * 32;        // 16 bf16 = 32 bytes
            uint32_t aH[2][4], aL[2][4], bH[4][4], bL[4][4];
#pragma unroll
            for (int mi = 0; mi < 2; mi++) {
                ldsm_x4(aH[mi], aHb + mi * (16 * ROW_B) + ko);
                ldsm_x4(aL[mi], aLb + mi * (16 * ROW_B) + ko);
            }
#pragma unroll
            for (int p = 0; p < 4; p++) {
                ldsm_x4(bH[p], bHb + p * (16 * ROW_B) + ko);
                ldsm_x4(bL[p], bLb + p * (16 * ROW_B) + ko);
            }
            // pass-major: consecutive MMAs never share an accumulator (no RAW)
#pragma unroll
            for (int mi = 0; mi < 2; mi++)
#pragma unroll
                for (int p = 0; p < 4; p++) {
                    mma_bf16(d[mi][2 * p],     aH[mi], bH[p][0], bH[p][2]);
                    mma_bf16(d[mi][2 * p + 1], aH[mi], bH[p][1], bH[p][3]);
                }
#pragma unroll
            for (int mi = 0; mi < 2; mi++)
#pragma unroll
                for (int p = 0; p < 4; p++) {
                    mma_bf16(d[mi][2 * p],     aH[mi], bL[p][0], bL[p][2]);
                    mma_bf16(d[mi][2 * p + 1], aH[mi], bL[p][1], bL[p][3]);
                }
#pragma unroll
            for (int mi = 0; mi < 2; mi++)
#pragma unroll
                for (int p = 0; p < 4; p++) {
                    mma_bf16(d[mi][2 * p],     aL[mi], bH[p][0], bH[p][2]);
                    mma_bf16(d[mi][2 * p + 1], aL[mi], bH[p][1], bH[p][3]);
                }
        }
        __syncthreads();
    }

    // Epilogue: direct float2 stores + bias
#pragma unroll
    for (int nj = 0; nj < 8; nj++) {
        int cc = n0 + wn * 64 + nj * 8 + 2 * t;
        float2 bv = *(const float2*)&bias[cc];
#pragma unroll
        for (int mi = 0; mi < 2; mi++) {
            int r0 = m0 + wm * 32 + mi * 16 + g;
            float2 o0 = {d[mi][nj][0] + bv.x, d[mi][nj][1] + bv.y};
            float2 o1 = {d[mi][nj][2] + bv.x, d[mi][nj][3] + bv.y};
            *(float2*)&C[(size_t)r0 * OUT_DIM + cc]       = o0;
            *(float2*)&C[(size_t)(r0 + 8) * OUT_DIM + cc] = o1;
        }
    }
}

// ======================= LIF sequential scan ================================
// 2 batch streams per CTA (1024 threads): barrier cost amortized over 2 b's.
// Thread = (stream s = tid>>9, neuron o = tid&511). Warps never straddle streams.
__device__ __forceinline__ void lif_step(
    float c, float& v, float& z, int& anySpike,
    unsigned (*smask)[16], int s, int o, int wid, int lane,
    float d, float omd,
    float* __restrict__ outB, float* __restrict__ svB, float* __restrict__ szB,
    int t)
{
    float soma = c;
    if (anySpike) {
#pragma unroll 1
        for (int w = 0; w < OUT_DIM / 32; w++) {
            unsigned m = smask[s][w];
            while (m) {
                int j = w * 32 + (__ffs(m) - 1);
                m &= (m - 1);
                soma += g_RT[(size_t)j * OUT_DIM + o];
            }
        }
    }
    v = d * (v * (1.f - z)) + omd * soma;
    z = (v >= 1.f) ? 1.f : 0.f;
    outB[(size_t)t * OUT_DIM + o]      = z;
    svB[(size_t)(t + 1) * OUT_DIM + o] = v;
    szB[(size_t)(t + 1) * OUT_DIM + o] = z;
    unsigned bal = __ballot_sync(0xffffffffu, z > 0.f);
    anySpike = __syncthreads_count(z > 0.f);   // barrier: mask reads / writes split
    if (anySpike) {                            // block-uniform; must refresh BOTH
        if (lane == 0) smask[s][wid] = bal;    // streams' masks (may be all-zero)
        __syncthreads();
    }
}

__global__ __launch_bounds__(1024, 1)
void scan_kernel(const float* __restrict__ cur,
                 const float* __restrict__ decay,
                 float* __restrict__ outputs,
                 float* __restrict__ statesV,
                 float* __restrict__ statesZ,
                 int T) {
    const int tid  = threadIdx.x;
    const int nst  = blockDim.x >> 9;          // streams per CTA (1 or 2)
    const int s    = tid >> 9;
    const int o    = tid & 511;
    const int wid  = o >> 5, lane = o & 31;
    const int b    = blockIdx.x * nst + s;

    __shared__ unsigned smask[2][16];
    if (tid < 32) smask[tid >> 4][tid & 15] = 0u;

    const float d   = decay[o];
    const float omd = 1.f - d;

    const float* curB = cur     + (size_t)b * T * OUT_DIM;
    float* outB = outputs + (size_t)b * T * OUT_DIM;
    float* svB  = statesV + (size_t)b * (T + 1) * OUT_DIM;
    float* szB  = statesZ + (size_t)b * (T + 1) * OUT_DIM;

    svB[o] = 0.f;
    szB[o] = 0.f;

    float v = 0.f, z = 0.f;
    int anySpike = 0;
    __syncthreads();

    float c0 = 0.f, c1 = 0.f, c2 = 0.f, c3 = 0.f;
    if (T > 0) c0 = curB[o];
    if (T > 1) c1 = curB[(size_t)OUT_DIM + o];
    if (T > 2) c2 = curB[(size_t)2 * OUT_DIM + o];
    if (T > 3) c3 = curB[(size_t)3 * OUT_DIM + o];

    int t = 0;
#pragma unroll 1
    for (; t + 3 < T; t += 4) {
        float n0 = (t + 4 < T) ? curB[(size_t)(t + 4) * OUT_DIM + o] : 0.f;
        lif_step(c0, v, z, anySpike, smask, s, o, wid, lane, d, omd, outB, svB, szB, t);
        float n1 = (t + 5 < T) ? curB[(size_t)(t + 5) * OUT_DIM + o] : 0.f;
        lif_step(c1, v, z, anySpike, smask, s, o, wid, lane, d, omd, outB, svB, szB, t + 1);
        float n2 = (t + 6 < T) ? curB[(size_t)(t + 6) * OUT_DIM + o] : 0.f;
        lif_step(c2, v, z, anySpike, smask, s, o, wid, lane, d, omd, outB, svB, szB, t + 2);
        float n3 = (t + 7 < T) ? curB[(size_t)(t + 7) * OUT_DIM + o] : 0.f;
        lif_step(c3, v, z, anySpike, smask, s, o, wid, lane, d, omd, outB, svB, szB, t + 3);
        c0 = n0; c1 = n1; c2 = n2; c3 = n3;
    }
    if (t < T) { lif_step(c0, v, z, anySpike, smask, s, o, wid, lane, d, omd, outB, svB, szB, t); t++; }
    if (t < T) { lif_step(c1, v, z, anySpike, smask, s, o, wid, lane, d, omd, outB, svB, szB, t); t++; }
    if (t < T) { lif_step(c2, v, z, anySpike, smask, s, o, wid, lane, d, omd, outB, svB, szB, t); t++; }
}

// ---------------------------------------------------------------------------
extern "C" void kernel_launch(void* const* d_in, const int* in_sizes, int n_in,
                              void* d_out, int out_size) {
    const float* x      = (const float*)d_in[0];  // [B, T, IN]
    const float* weight = (const float*)d_in[1];  // [OUT, IN]
    const float* bias   = (const float*)d_in[2];  // [OUT]
    const float* recur  = (const float*)d_in[3];  // [OUT, OUT]
    const float* decay  = (const float*)d_in[4];  // [OUT]

    const int OUT = in_sizes[2];                         // 512
    const int IN  = in_sizes[1] / OUT;                   // 512
    const long long M = (long long)in_sizes[0] / IN;     // B*T
    const long long B = (((long long)out_size / OUT) - 3 * M) / 2;
    const int T = (int)(M / B);

    float* outputs = (float*)d_out;                        // [B,T,OUT]
    float* statesV = outputs + (size_t)B * T * OUT;        // [B,T+1,OUT]
    float* statesZ = statesV + (size_t)B * (T + 1) * OUT;  // [B,T+1,OUT]
    // cur aliases outputs: cur[b,t,o] read (<=4 steps early) strictly before
    // outputs[b,t,o] is written by the same thread; indices coincide 1:1.
    float* cur = outputs;

    long long n4x = M * IN / 4;
    convert_x_kernel<<<(unsigned)((n4x + 255) / 256), 256>>>(x, n4x);
    convert_w_kernel<<<(OUT * IN / 4) / 256, 256>>>(weight);

    {
        dim3 grid(OUT / 32, OUT / 32), block(32, 32);
        transpose512_kernel<<<grid, block>>>(recur);
    }

    cudaFuncSetAttribute(gemm_hmma_kernel,
                         cudaFuncAttributeMaxDynamicSharedMemorySize, SMEM_GEMM);
    {
        dim3 grid(OUT / 128, (unsigned)(M / 128));   // n fastest -> A reuse in L2
        gemm_hmma_kernel<<<grid, 256, SMEM_GEMM>>>(bias, cur);
    }

    if (B % 2 == 0) {
        scan_kernel<<<(unsigned)(B / 2), 1024>>>(cur, decay, outputs, statesV, statesZ, T);
    } else {
        scan_kernel<<<(unsigned)B, 512>>>(cur, decay, outputs, statesV, statesZ, T);
    }
}

// round 8
// speedup vs baseline: 1.1434x; 1.0031x over previous
#include <cuda_runtime.h>
#include <cuda_bf16.h>
#include <cstdint>

// ---------------------------------------------------------------------------
// LIF layer forward (sm_103 base ISA):
//   cur = x @ W^T + bias   (3-pass split-bf16 HMMA GEMM, ldmatrix feeds)
//   scan: v = d*v*(1-z) + (1-d)*(cur_t + z @ R^T);  z = (v >= 1)
// d_out = [outputs | statesV | statesZ]
// ---------------------------------------------------------------------------

#define IN_DIM  512
#define OUT_DIM 512
#define MAX_M   64000

__device__ __nv_bfloat16 g_xhi[(size_t)MAX_M * IN_DIM];
__device__ __nv_bfloat16 g_xlo[(size_t)MAX_M * IN_DIM];
__device__ __nv_bfloat16 g_whi[(size_t)OUT_DIM * IN_DIM];
__device__ __nv_bfloat16 g_wlo[(size_t)OUT_DIM * IN_DIM];
__device__ float         g_RT [(size_t)OUT_DIM * OUT_DIM];

// ======================= conversion kernels =================================
__global__ void convert_x_kernel(const float* __restrict__ x, long long n4) {
    long long i = (long long)blockIdx.x * blockDim.x + threadIdx.x;
    if (i >= n4) return;
    float4 v = ((const float4*)x)[i];
    float vv[4] = {v.x, v.y, v.z, v.w};
    __nv_bfloat16 h[4], l[4];
#pragma unroll
    for (int k = 0; k < 4; k++) {
        h[k] = __float2bfloat16_rn(vv[k]);
        l[k] = __float2bfloat16_rn(vv[k] - __bfloat162float(h[k]));
    }
    __nv_bfloat162* hi2 = (__nv_bfloat162*)g_xhi;
    __nv_bfloat162* lo2 = (__nv_bfloat162*)g_xlo;
    hi2[i * 2]     = __halves2bfloat162(h[0], h[1]);
    hi2[i * 2 + 1] = __halves2bfloat162(h[2], h[3]);
    lo2[i * 2]     = __halves2bfloat162(l[0], l[1]);
    lo2[i * 2 + 1] = __halves2bfloat162(l[2], l[3]);
}

__global__ void convert_w_kernel(const float* __restrict__ w) {
    int i = blockIdx.x * blockDim.x + threadIdx.x;
    float4 v = ((const float4*)w)[i];
    float vv[4] = {v.x, v.y, v.z, v.w};
    __nv_bfloat16 h[4], l[4];
#pragma unroll
    for (int k = 0; k < 4; k++) {
        h[k] = __float2bfloat16_rn(vv[k]);
        l[k] = __float2bfloat16_rn(vv[k] - __bfloat162float(h[k]));
    }
    __nv_bfloat162* hi2 = (__nv_bfloat162*)g_whi;
    __nv_bfloat162* lo2 = (__nv_bfloat162*)g_wlo;
    hi2[i * 2]     = __halves2bfloat162(h[0], h[1]);
    hi2[i * 2 + 1] = __halves2bfloat162(h[2], h[3]);
    lo2[i * 2]     = __halves2bfloat162(l[0], l[1]);
    lo2[i * 2 + 1] = __halves2bfloat162(l[2], l[3]);
}

__global__ void transpose512_kernel(const float* __restrict__ R) {
    __shared__ float tile[32][33];
    int x = blockIdx.x * 32 + threadIdx.x;
    int y = blockIdx.y * 32 + threadIdx.y;
    tile[threadIdx.y][threadIdx.x] = R[y * OUT_DIM + x];
    __syncthreads();
    int xo = blockIdx.y * 32 + threadIdx.x;
    int yo = blockIdx.x * 32 + threadIdx.y;
    g_RT[yo * OUT_DIM + xo] = tile[threadIdx.x][threadIdx.y];
}

// ======================= HMMA GEMM ==========================================
// CTA 128x128, BK=32 (16 stages), double-buffered cp.async, 2 CTAs/SM.
// Warp grid 4(m) x 2(n); warp tile 32x64; ldmatrix.x4 fragment loads.
// SMEM rows: 32 bf16 = 64 B + 16 pad = 80 B stride (bank16 = 5r mod 32:
// any 8 consecutive rows hit distinct 16B banks -> ldmatrix conflict-free).
#define ROW_B     80
#define PART_B    (128 * ROW_B)                 // 10240
#define STAGE_B   (4 * PART_B)                  // 40960
#define SMEM_GEMM (2 * STAGE_B)                 // 81920 (2 CTAs/SM fit)

__device__ __forceinline__ uint32_t smem_u32(const void* p) {
    uint32_t a;
    asm("{ .reg .u64 t; cvta.to.shared.u64 t, %1; cvt.u32.u64 %0, t; }"
        : "=r"(a) : "l"(p));
    return a;
}

__device__ __forceinline__ void cp16(uint32_t dst, const void* src) {
    asm volatile("cp.async.cg.shared.global [%0], [%1], 16;" :: "r"(dst), "l"(src));
}

__device__ __forceinline__ void ldsm_x4(uint32_t* r, uint32_t addr) {
    asm volatile("ldmatrix.sync.aligned.m8n8.x4.shared.b16 {%0,%1,%2,%3}, [%4];"
        : "=r"(r[0]), "=r"(r[1]), "=r"(r[2]), "=r"(r[3]) : "r"(addr));
}

__device__ __forceinline__ void mma_bf16(float* d, const uint32_t* a,
                                         uint32_t b0, uint32_t b1) {
    asm volatile(
        "mma.sync.aligned.m16n8k16.row.col.f32.bf16.bf16.f32 "
        "{%0,%1,%2,%3}, {%4,%5,%6,%7}, {%8,%9}, {%0,%1,%2,%3};"
        : "+f"(d[0]), "+f"(d[1]), "+f"(d[2]), "+f"(d[3])
        : "r"(a[0]), "r"(a[1]), "r"(a[2]), "r"(a[3]), "r"(b0), "r"(b1));
}

__device__ __forceinline__ void load_stage(uint32_t sbase, int buf,
        const __nv_bfloat16* Ah, const __nv_bfloat16* Al,
        const __nv_bfloat16* Bh, const __nv_bfloat16* Bl,
        int k0, int tid) {
    uint32_t base = sbase + buf * STAGE_B;
    const __nv_bfloat16* srcs[4] = {Ah, Al, Bh, Bl};
#pragma unroll
    for (int p = 0; p < 4; p++) {
        uint32_t pb = base + p * PART_B;
        const __nv_bfloat16* gp = srcs[p] + k0;
#pragma unroll
        for (int it = 0; it < 2; it++) {        // 512 chunks: 128 rows x 4x16B
            int chunk = it * 256 + tid;
            int row = chunk >> 2;
            int cc  = chunk & 3;
            cp16(pb + row * ROW_B + cc * 16,
                 gp + (size_t)row * IN_DIM + cc * 8);
        }
    }
    asm volatile("cp.async.commit_group;");
}

__global__ __launch_bounds__(256, 2)
void gemm_hmma_kernel(const float* __restrict__ bias, float* __restrict__ C) {
    extern __shared__ char sm[];
    const uint32_t sbase = smem_u32(sm);
    const int tid  = threadIdx.x;
    const int wid  = tid >> 5;
    const int lane = tid & 31;
    const int g = lane >> 2, t = lane & 3;
    const int wm = wid >> 1;
    const int wn = wid & 1;
    // n varies fastest across CTA ids -> A rows reused by 4 consecutive CTAs
    const int n0 = blockIdx.x * 128;
    const int m0 = blockIdx.y * 128;

    const __nv_bfloat16* Ah = g_xhi + (size_t)m0 * IN_DIM;
    const __nv_bfloat16* Al = g_xlo + (size_t)m0 * IN_DIM;
    const __nv_bfloat16* Bh = g_whi + (size_t)n0 * IN_DIM;
    const __nv_bfloat16* Bl = g_wlo + (size_t)n0 * IN_DIM;

    const uint32_t aRowOff = (uint32_t)(wm * 32 + (lane & 15)) * ROW_B + (lane >> 4) * 16;
    const uint32_t bRowOff = (uint32_t)(wn * 64 + (lane & 15)) * ROW_B + (lane >> 4) * 16;

    float d[2][8][4];
#pragma unroll
    for (int mi = 0; mi < 2; mi++)
#pragma unroll
        for (int nj = 0; nj < 8; nj++)
#pragma unroll
            for (int r = 0; r < 4; r++) d[mi][nj][r] = 0.f;

    load_stage(sbase, 0, Ah, Al, Bh, Bl, 0, tid);

#pragma unroll 1
    for (int s = 0; s < 16; s++) {
        if (s < 15) {
            load_stage(sbase, (s + 1) & 1, Ah, Al, Bh, Bl, (s + 1) * 32, tid);
            asm volatile("cp.async.wait_group 1;");
        } else {
            asm volatile("cp.async.wait_group 0;");
        }
        __syncthreads();

        const uint32_t stg = sbase + (s & 1) * STAGE_B;
        const uint32_t aHb = stg              + aRowOff;
        const uint32_t aLb = stg + PART_B     + aRowOff;
        const uint32_t bHb = stg + 2 * PART_B + bRowOff;
        const uint32_t bLb = stg + 3 * PART_B + bRowOff;

#pragma unroll
        for (int kk = 0; kk < 2; kk++) {
            const uint32_t ko = kk * 32;        // 16 bf16 = 32 bytes
            uint32_t aH[2][4], aL[2][4], bH[4][4], bL[4][4];
#pragma unroll
            for (int mi = 0; mi < 2; mi++) {
                ldsm_x4(aH[mi], aHb + mi * (16 * ROW_B) + ko);
                ldsm_x4(aL[mi], aLb + mi * (16 * ROW_B) + ko);
            }
#pragma unroll
            for (int p = 0; p < 4; p++) {
                ldsm_x4(bH[p], bHb + p * (16 * ROW_B) + ko);
                ldsm_x4(bL[p], bLb + p * (16 * ROW_B) + ko);
            }
            // pass-major: consecutive MMAs never share an accumulator (no RAW)
#pragma unroll
            for (int mi = 0; mi < 2; mi++)
#pragma unroll
                for (int p = 0; p < 4; p++) {
                    mma_bf16(d[mi][2 * p],     aH[mi], bH[p][0], bH[p][2]);
                    mma_bf16(d[mi][2 * p + 1], aH[mi], bH[p][1], bH[p][3]);
                }
#pragma unroll
            for (int mi = 0; mi < 2; mi++)
#pragma unroll
                for (int p = 0; p < 4; p++) {
                    mma_bf16(d[mi][2 * p],     aH[mi], bL[p][0], bL[p][2]);
                    mma_bf16(d[mi][2 * p + 1], aH[mi], bL[p][1], bL[p][3]);
                }
#pragma unroll
            for (int mi = 0; mi < 2; mi++)
#pragma unroll
                for (int p = 0; p < 4; p++) {
                    mma_bf16(d[mi][2 * p],     aL[mi], bH[p][0], bH[p][2]);
                    mma_bf16(d[mi][2 * p + 1], aL[mi], bH[p][1], bH[p][3]);
                }
        }
        __syncthreads();
    }

    // Epilogue: direct float2 stores + bias
#pragma unroll
    for (int nj = 0; nj < 8; nj++) {
        int cc = n0 + wn * 64 + nj * 8 + 2 * t;
        float2 bv = *(const float2*)&bias[cc];
#pragma unroll
        for (int mi = 0; mi < 2; mi++) {
            int r0 = m0 + wm * 32 + mi * 16 + g;
            float2 o0 = {d[mi][nj][0] + bv.x, d[mi][nj][1] + bv.y};
            float2 o1 = {d[mi][nj][2] + bv.x, d[mi][nj][3] + bv.y};
            *(float2*)&C[(size_t)r0 * OUT_DIM + cc]       = o0;
            *(float2*)&C[(size_t)(r0 + 8) * OUT_DIM + cc] = o1;
        }
    }
}

// ======================= LIF sequential scan ================================
// 2 batch streams per CTA (1024 threads): barrier cost amortized over 2 b's.
// Thread = (stream s = tid>>9, neuron o = tid&511). Warps never straddle streams.
__device__ __forceinline__ void lif_step(
    float c, float& v, float& z, int& anySpike,
    unsigned (*smask)[16], int s, int o, int wid, int lane,
    float d, float omd,
    float* __restrict__ outB, float* __restrict__ svB, float* __restrict__ szB,
    int t)
{
    float soma = c;
    if (anySpike) {
#pragma unroll 1
        for (int w = 0; w < OUT_DIM / 32; w++) {
            unsigned m = smask[s][w];
            while (m) {
                int j = w * 32 + (__ffs(m) - 1);
                m &= (m - 1);
                soma += g_RT[(size_t)j * OUT_DIM + o];
            }
        }
    }
    v = d * (v * (1.f - z)) + omd * soma;
    z = (v >= 1.f) ? 1.f : 0.f;
    outB[(size_t)t * OUT_DIM + o]      = z;
    svB[(size_t)(t + 1) * OUT_DIM + o] = v;
    szB[(size_t)(t + 1) * OUT_DIM + o] = z;
    unsigned bal = __ballot_sync(0xffffffffu, z > 0.f);
    anySpike = __syncthreads_count(z > 0.f);   // barrier: mask reads / writes split
    if (anySpike) {                            // block-uniform; must refresh BOTH
        if (lane == 0) smask[s][wid] = bal;    // streams' masks (may be all-zero)
        __syncthreads();
    }
}

__global__ __launch_bounds__(1024, 1)
void scan_kernel(const float* __restrict__ cur,
                 const float* __restrict__ decay,
                 float* __restrict__ outputs,
                 float* __restrict__ statesV,
                 float* __restrict__ statesZ,
                 int T) {
    const int tid  = threadIdx.x;
    const int nst  = blockDim.x >> 9;          // streams per CTA (1 or 2)
    const int s    = tid >> 9;
    const int o    = tid & 511;
    const int wid  = o >> 5, lane = o & 31;
    const int b    = blockIdx.x * nst + s;

    __shared__ unsigned smask[2][16];
    if (tid < 32) smask[tid >> 4][tid & 15] = 0u;

    const float d   = decay[o];
    const float omd = 1.f - d;

    const float* curB = cur     + (size_t)b * T * OUT_DIM;
    float* outB = outputs + (size_t)b * T * OUT_DIM;
    float* svB  = statesV + (size_t)b * (T + 1) * OUT_DIM;
    float* szB  = statesZ + (size_t)b * (T + 1) * OUT_DIM;

    svB[o] = 0.f;
    szB[o] = 0.f;

    float v = 0.f, z = 0.f;
    int anySpike = 0;
    __syncthreads();

    float c0 = 0.f, c1 = 0.f, c2 = 0.f, c3 = 0.f;
    if (T > 0) c0 = curB[o];
    if (T > 1) c1 = curB[(size_t)OUT_DIM + o];
    if (T > 2) c2 = curB[(size_t)2 * OUT_DIM + o];
    if (T > 3) c3 = curB[(size_t)3 * OUT_DIM + o];

    int t = 0;
#pragma unroll 1
    for (; t + 3 < T; t += 4) {
        float n0 = (t + 4 < T) ? curB[(size_t)(t + 4) * OUT_DIM + o] : 0.f;
        lif_step(c0, v, z, anySpike, smask, s, o, wid, lane, d, omd, outB, svB, szB, t);
        float n1 = (t + 5 < T) ? curB[(size_t)(t + 5) * OUT_DIM + o] : 0.f;
        lif_step(c1, v, z, anySpike, smask, s, o, wid, lane, d, omd, outB, svB, szB, t + 1);
        float n2 = (t + 6 < T) ? curB[(size_t)(t + 6) * OUT_DIM + o] : 0.f;
        lif_step(c2, v, z, anySpike, smask, s, o, wid, lane, d, omd, outB, svB, szB, t + 2);
        float n3 = (t + 7 < T) ? curB[(size_t)(t + 7) * OUT_DIM + o] : 0.f;
        lif_step(c3, v, z, anySpike, smask, s, o, wid, lane, d, omd, outB, svB, szB, t + 3);
        c0 = n0; c1 = n1; c2 = n2; c3 = n3;
    }
    if (t < T) { lif_step(c0, v, z, anySpike, smask, s, o, wid, lane, d, omd, outB, svB, szB, t); t++; }
    if (t < T) { lif_step(c1, v, z, anySpike, smask, s, o, wid, lane, d, omd, outB, svB, szB, t); t++; }
    if (t < T) { lif_step(c2, v, z, anySpike, smask, s, o, wid, lane, d, omd, outB, svB, szB, t); t++; }
}

// ---------------------------------------------------------------------------
extern "C" void kernel_launch(void* const* d_in, const int* in_sizes, int n_in,
                              void* d_out, int out_size) {
    const float* x      = (const float*)d_in[0];  // [B, T, IN]
    const float* weight = (const float*)d_in[1];  // [OUT, IN]
    const float* bias   = (const float*)d_in[2];  // [OUT]
    const float* recur  = (const float*)d_in[3];  // [OUT, OUT]
    const float* decay  = (const float*)d_in[4];  // [OUT]

    const int OUT = in_sizes[2];                         // 512
    const int IN  = in_sizes[1] / OUT;                   // 512
    const long long M = (long long)in_sizes[0] / IN;     // B*T
    const long long B = (((long long)out_size / OUT) - 3 * M) / 2;
    const int T = (int)(M / B);

    float* outputs = (float*)d_out;                        // [B,T,OUT]
    float* statesV = outputs + (size_t)B * T * OUT;        // [B,T+1,OUT]
    float* statesZ = statesV + (size_t)B * (T + 1) * OUT;  // [B,T+1,OUT]
    // cur aliases outputs: cur[b,t,o] read (<=4 steps early) strictly before
    // outputs[b,t,o] is written by the same thread; indices coincide 1:1.
    float* cur = outputs;

    long long n4x = M * IN / 4;
    convert_x_kernel<<<(unsigned)((n4x + 255) / 256), 256>>>(x, n4x);
    convert_w_kernel<<<(OUT * IN / 4) / 256, 256>>>(weight);

    {
        dim3 grid(OUT / 32, OUT / 32), block(32, 32);
        transpose512_kernel<<<grid, block>>>(recur);
    }

    cudaFuncSetAttribute(gemm_hmma_kernel,
                         cudaFuncAttributeMaxDynamicSharedMemorySize, SMEM_GEMM);
    {
        dim3 grid(OUT / 128, (unsigned)(M / 128));   // n fastest -> A reuse in L2
        gemm_hmma_kernel<<<grid, 256, SMEM_GEMM>>>(bias, cur);
    }

    if (B % 2 == 0) {
        scan_kernel<<<(unsigned)(B / 2), 1024>>>(cur, decay, outputs, statesV, statesZ, T);
    } else {
        scan_kernel<<<(unsigned)B, 512>>>(cur, decay, outputs, statesV, statesZ, T);
    }
}

// round 9
// speedup vs baseline: 1.4712x; 1.2866x over previous
#include <cuda_runtime.h>
#include <cuda_bf16.h>
#include <cstdint>

// ---------------------------------------------------------------------------
// LIF layer forward (sm_103 base ISA):
//   cur = x @ W^T + bias       (3-pass split-bf16 HMMA GEMM ~ fp32 precision)
//   scan: v = d*v*(1-z) + (1-d)*(cur_t + z @ R^T);  z = (v >= 1)
// Scan is chunk-parallelized on the (provably flagged) no-spike linear path,
// with an exact sequential fallback per batch element if any v >= THR.
// d_out = [outputs | statesV | statesZ]
// ---------------------------------------------------------------------------

#define IN_DIM  512
#define OUT_DIM 512
#define MAX_M   64000
#define MAX_B   128
#define CH      125          // chunk length for parallel scan
#define MAX_NCH 16

__device__ __nv_bfloat16 g_xhi[(size_t)MAX_M * IN_DIM];
__device__ __nv_bfloat16 g_xlo[(size_t)MAX_M * IN_DIM];
__device__ __nv_bfloat16 g_whi[(size_t)OUT_DIM * IN_DIM];
__device__ __nv_bfloat16 g_wlo[(size_t)OUT_DIM * IN_DIM];
__device__ float         g_RT [(size_t)OUT_DIM * OUT_DIM];
__device__ float         g_cur[(size_t)MAX_M * OUT_DIM];          // 131 MB
__device__ float         g_csum  [(size_t)MAX_B * MAX_NCH * OUT_DIM];
__device__ float         g_vbound[(size_t)MAX_B * MAX_NCH * OUT_DIM];
__device__ int           g_flag[MAX_B];

// ======================= conversion kernels =================================
__global__ void convert_x_kernel(const float* __restrict__ x, long long n4) {
    long long i = (long long)blockIdx.x * blockDim.x + threadIdx.x;
    if (i >= n4) return;
    float4 v = ((const float4*)x)[i];
    float vv[4] = {v.x, v.y, v.z, v.w};
    __nv_bfloat16 h[4], l[4];
#pragma unroll
    for (int k = 0; k < 4; k++) {
        h[k] = __float2bfloat16_rn(vv[k]);
        l[k] = __float2bfloat16_rn(vv[k] - __bfloat162float(h[k]));
    }
    __nv_bfloat162* hi2 = (__nv_bfloat162*)g_xhi;
    __nv_bfloat162* lo2 = (__nv_bfloat162*)g_xlo;
    hi2[i * 2]     = __halves2bfloat162(h[0], h[1]);
    hi2[i * 2 + 1] = __halves2bfloat162(h[2], h[3]);
    lo2[i * 2]     = __halves2bfloat162(l[0], l[1]);
    lo2[i * 2 + 1] = __halves2bfloat162(l[2], l[3]);
}

__global__ void convert_w_kernel(const float* __restrict__ w) {
    int i = blockIdx.x * blockDim.x + threadIdx.x;
    float4 v = ((const float4*)w)[i];
    float vv[4] = {v.x, v.y, v.z, v.w};
    __nv_bfloat16 h[4], l[4];
#pragma unroll
    for (int k = 0; k < 4; k++) {
        h[k] = __float2bfloat16_rn(vv[k]);
        l[k] = __float2bfloat16_rn(vv[k] - __bfloat162float(h[k]));
    }
    __nv_bfloat162* hi2 = (__nv_bfloat162*)g_whi;
    __nv_bfloat162* lo2 = (__nv_bfloat162*)g_wlo;
    hi2[i * 2]     = __halves2bfloat162(h[0], h[1]);
    hi2[i * 2 + 1] = __halves2bfloat162(h[2], h[3]);
    lo2[i * 2]     = __halves2bfloat162(l[0], l[1]);
    lo2[i * 2 + 1] = __halves2bfloat162(l[2], l[3]);
}

__global__ void transpose512_kernel(const float* __restrict__ R) {
    __shared__ float tile[32][33];
    int x = blockIdx.x * 32 + threadIdx.x;
    int y = blockIdx.y * 32 + threadIdx.y;
    tile[threadIdx.y][threadIdx.x] = R[y * OUT_DIM + x];
    __syncthreads();
    int xo = blockIdx.y * 32 + threadIdx.x;
    int yo = blockIdx.x * 32 + threadIdx.y;
    g_RT[yo * OUT_DIM + xo] = tile[threadIdx.x][threadIdx.y];
}

// ======================= HMMA GEMM (R5-proven config) =======================
// CTA 128x128, BK=64 (8 stages), double-buffered cp.async, scalar LDS feeds.
#define TSTRIDE   72
#define PART_B    (128 * TSTRIDE * 2)          // 18432
#define STAGE_B   (4 * PART_B)                 // 73728
#define SMEM_GEMM (2 * STAGE_B)                // 147456

__device__ __forceinline__ void cp16(void* dst, const void* src) {
    uint32_t d;
    asm("{ .reg .u64 t; cvta.to.shared.u64 t, %1; cvt.u32.u64 %0, t; }"
        : "=r"(d) : "l"(dst));
    asm volatile("cp.async.cg.shared.global [%0], [%1], 16;" :: "r"(d), "l"(src));
}

__device__ __forceinline__ void mma_bf16(float* d, const uint32_t* a,
                                         const uint32_t* b) {
    asm volatile(
        "mma.sync.aligned.m16n8k16.row.col.f32.bf16.bf16.f32 "
        "{%0,%1,%2,%3}, {%4,%5,%6,%7}, {%8,%9}, {%0,%1,%2,%3};"
        : "+f"(d[0]), "+f"(d[1]), "+f"(d[2]), "+f"(d[3])
        : "r"(a[0]), "r"(a[1]), "r"(a[2]), "r"(a[3]), "r"(b[0]), "r"(b[1]));
}

__device__ __forceinline__ void load_stage(char* sm, int buf,
        const __nv_bfloat16* Ah, const __nv_bfloat16* Al,
        const __nv_bfloat16* Bh, const __nv_bfloat16* Bl,
        int k0, int tid) {
    char* base = sm + buf * STAGE_B;
    const __nv_bfloat16* srcs[4] = {Ah, Al, Bh, Bl};
#pragma unroll
    for (int p = 0; p < 4; p++) {
        char* pb = base + p * PART_B;
        const __nv_bfloat16* gp = srcs[p] + k0;
#pragma unroll
        for (int it = 0; it < 4; it++) {
            int chunk = it * 256 + tid;
            int row = chunk >> 3;
            int cc  = chunk & 7;
            cp16(pb + row * (TSTRIDE * 2) + cc * 16,
                 gp + (size_t)row * IN_DIM + cc * 8);
        }
    }
    asm volatile("cp.async.commit_group;");
}

__global__ __launch_bounds__(256)
void gemm_hmma_kernel(const float* __restrict__ bias, float* __restrict__ C) {
    extern __shared__ char sm[];
    const int tid  = threadIdx.x;
    const int wid  = tid >> 5;
    const int lane = tid & 31;
    const int g = lane >> 2, t = lane & 3;
    const int wm = wid >> 1;
    const int wn = wid & 1;
    const int m0 = blockIdx.x * 128;
    const int n0 = blockIdx.y * 128;

    const __nv_bfloat16* Ah = g_xhi + (size_t)m0 * IN_DIM;
    const __nv_bfloat16* Al = g_xlo + (size_t)m0 * IN_DIM;
    const __nv_bfloat16* Bh = g_whi + (size_t)n0 * IN_DIM;
    const __nv_bfloat16* Bl = g_wlo + (size_t)n0 * IN_DIM;

    float d[2][8][4];
#pragma unroll
    for (int mi = 0; mi < 2; mi++)
#pragma unroll
        for (int nj = 0; nj < 8; nj++)
#pragma unroll
            for (int r = 0; r < 4; r++) d[mi][nj][r] = 0.f;

    load_stage(sm, 0, Ah, Al, Bh, Bl, 0, tid);

#pragma unroll 1
    for (int s = 0; s < 8; s++) {
        if (s < 7) {
            load_stage(sm, (s + 1) & 1, Ah, Al, Bh, Bl, (s + 1) * 64, tid);
            asm volatile("cp.async.wait_group 1;");
        } else {
            asm volatile("cp.async.wait_group 0;");
        }
        __syncthreads();

        const uint32_t* As = (const uint32_t*)(sm + (s & 1) * STAGE_B);
        const uint32_t* Als = As + PART_B / 4;
        const uint32_t* Bs  = As + 2 * (PART_B / 4);
        const uint32_t* Bls = As + 3 * (PART_B / 4);
        const int HS = TSTRIDE / 2;

#pragma unroll
        for (int kk = 0; kk < 4; kk++) {
            uint32_t ah[2][4], al[2][4];
#pragma unroll
            for (int mi = 0; mi < 2; mi++) {
                int r0 = wm * 32 + mi * 16 + g;
                int cb = kk * 8 + t;
                ah[mi][0] = As [r0 * HS + cb];
                ah[mi][1] = As [(r0 + 8) * HS + cb];
                ah[mi][2] = As [r0 * HS + cb + 4];
                ah[mi][3] = As [(r0 + 8) * HS + cb + 4];
                al[mi][0] = Als[r0 * HS + cb];
                al[mi][1] = Als[(r0 + 8) * HS + cb];
                al[mi][2] = Als[r0 * HS + cb + 4];
                al[mi][3] = Als[(r0 + 8) * HS + cb + 4];
            }
            uint32_t bh[8][2], bl[8][2];
#pragma unroll
            for (int nj = 0; nj < 8; nj++) {
                int rn = wn * 64 + nj * 8 + g;
                int cb = kk * 8 + t;
                bh[nj][0] = Bs [rn * HS + cb];
                bh[nj][1] = Bs [rn * HS + cb + 4];
                bl[nj][0] = Bls[rn * HS + cb];
                bl[nj][1] = Bls[rn * HS + cb + 4];
            }
#pragma unroll
            for (int mi = 0; mi < 2; mi++)
#pragma unroll
                for (int nj = 0; nj < 8; nj++) {
                    mma_bf16(d[mi][nj], ah[mi], bh[nj]);
                    mma_bf16(d[mi][nj], ah[mi], bl[nj]);
                    mma_bf16(d[mi][nj], al[mi], bh[nj]);
                }
        }
        __syncthreads();
    }

#pragma unroll
    for (int nj = 0; nj < 8; nj++) {
        int cc = n0 + wn * 64 + nj * 8 + 2 * t;
        float2 bv = *(const float2*)&bias[cc];
#pragma unroll
        for (int mi = 0; mi < 2; mi++) {
            int r0 = m0 + wm * 32 + mi * 16 + g;
            float2 o0 = {d[mi][nj][0] + bv.x, d[mi][nj][1] + bv.y};
            float2 o1 = {d[mi][nj][2] + bv.x, d[mi][nj][3] + bv.y};
            *(float2*)&C[(size_t)r0 * OUT_DIM + cc]       = o0;
            *(float2*)&C[(size_t)(r0 + 8) * OUT_DIM + cc] = o1;
        }
    }
}

// ================= Parallel scan, stage 1: chunk-local EMA sums ==============
// block = 512 threads (one o each); grid = B*NCH; chunk ch of batch b.
__global__ __launch_bounds__(OUT_DIM)
void scan_s1_kernel(const float* __restrict__ decay, int T, int NCH) {
    const int bc = blockIdx.x;
    const int b  = bc / NCH;
    const int ch = bc % NCH;
    const int o  = threadIdx.x;
    if (ch == 0 && o == 0) g_flag[b] = 0;      // re-zero each replay

    const float d = decay[o];
    const float omd = 1.f - d;
    const int t0 = ch * CH;
    const int t1 = min(T, t0 + CH);
    const float* curB = g_cur + ((size_t)b * T + t0) * OUT_DIM + o;

    float s = 0.f;
#pragma unroll 1
    for (int t = t0; t < t1; t++) {
        s = d * s + omd * (*curB);
        curB += OUT_DIM;
    }
    g_csum[(size_t)bc * OUT_DIM + o] = s;
}

// ================= stage 2: combine chunk boundaries ========================
// block = 512 (one o each); grid = B.
__global__ __launch_bounds__(OUT_DIM)
void scan_s2_kernel(const float* __restrict__ decay, int T, int NCH) {
    const int b = blockIdx.x;
    const int o = threadIdx.x;
    const float d = decay[o];

    float dpCH = 1.f;
#pragma unroll 1
    for (int i = 0; i < CH; i++) dpCH *= d;

    float vb = 0.f;
#pragma unroll 1
    for (int ch = 0; ch < NCH; ch++) {
        g_vbound[((size_t)b * NCH + ch) * OUT_DIM + o] = vb;
        int len = min(CH, T - ch * CH);
        float dp = dpCH;
        if (len != CH) { dp = 1.f; for (int i = 0; i < len; i++) dp *= d; }
        vb = dp * vb + g_csum[((size_t)b * NCH + ch) * OUT_DIM + o];
    }
}

// ================= stage 3: expand no-spike trajectory + flag ================
// block = 512; grid = B*NCH. Writes outputs/statesV/statesZ assuming z==0;
// flags batch if any v >= 1 (then S4 recomputes that batch exactly).
__global__ __launch_bounds__(OUT_DIM)
void scan_s3_kernel(const float* __restrict__ decay, int T, int NCH,
                    float* __restrict__ outputs,
                    float* __restrict__ statesV,
                    float* __restrict__ statesZ) {
    const int bc = blockIdx.x;
    const int b  = bc / NCH;
    const int ch = bc % NCH;
    const int o  = threadIdx.x;

    const float d = decay[o];
    const float omd = 1.f - d;
    const int t0 = ch * CH;
    const int t1 = min(T, t0 + CH);

    const float* curB = g_cur + ((size_t)b * T + t0) * OUT_DIM + o;
    float* outB = outputs + ((size_t)b * T + t0) * OUT_DIM + o;
    float* svB  = statesV + ((size_t)b * (T + 1) + t0 + 1) * OUT_DIM + o;
    float* szB  = statesZ + ((size_t)b * (T + 1) + t0 + 1) * OUT_DIM + o;

    if (ch == 0) {
        statesV[((size_t)b * (T + 1)) * OUT_DIM + o] = 0.f;
        statesZ[((size_t)b * (T + 1)) * OUT_DIM + o] = 0.f;
    }

    float v = g_vbound[(size_t)bc * OUT_DIM + o];
    bool spike = false;
#pragma unroll 1
    for (int t = t0; t < t1; t++) {
        v = d * v + omd * (*curB);
        float z = (v >= 1.f) ? 1.f : 0.f;
        spike |= (z > 0.f);
        *outB = z;  *svB = v;  *szB = z;
        curB += OUT_DIM; outB += OUT_DIM; svB += OUT_DIM; szB += OUT_DIM;
    }
    if (__syncthreads_or(spike)) {
        if (o == 0) atomicOr(&g_flag[b], 1);
    }
}

// ================= stage 4: exact sequential fallback (flagged only) ========
__device__ __forceinline__ void lif_step(
    float c, float& v, float& z, int& anySpike,
    unsigned* smask, int o, int wid, int lane,
    float d, float omd,
    float* __restrict__ outB, float* __restrict__ svB, float* __restrict__ szB,
    int t)
{
    float soma = c;
    if (anySpike) {
#pragma unroll 1
        for (int w = 0; w < OUT_DIM / 32; w++) {
            unsigned m = smask[w];
            while (m) {
                int j = w * 32 + (__ffs(m) - 1);
                m &= (m - 1);
                soma += g_RT[(size_t)j * OUT_DIM + o];
            }
        }
    }
    v = d * (v * (1.f - z)) + omd * soma;
    z = (v >= 1.f) ? 1.f : 0.f;
    outB[(size_t)t * OUT_DIM + o]      = z;
    svB[(size_t)(t + 1) * OUT_DIM + o] = v;
    szB[(size_t)(t + 1) * OUT_DIM + o] = z;
    unsigned bal = __ballot_sync(0xffffffffu, z > 0.f);
    anySpike = __syncthreads_count(z > 0.f);
    if (anySpike) {
        if (lane == 0) smask[wid] = bal;
        __syncthreads();
    }
}

__global__ __launch_bounds__(OUT_DIM, 1)
void scan_s4_kernel(const float* __restrict__ decay,
                    float* __restrict__ outputs,
                    float* __restrict__ statesV,
                    float* __restrict__ statesZ,
                    int T) {
    const int b = blockIdx.x;
    if (g_flag[b] == 0) return;                 // no spikes: S3 result is exact
    const int o = threadIdx.x;
    const int wid = o >> 5, lane = o & 31;

    __shared__ unsigned smask[OUT_DIM / 32];
    if (o < OUT_DIM / 32) smask[o] = 0u;

    const float d   = decay[o];
    const float omd = 1.f - d;

    const float* curB = g_cur + (size_t)b * T * OUT_DIM;
    float* outB = outputs + (size_t)b * T * OUT_DIM;
    float* svB  = statesV + (size_t)b * (T + 1) * OUT_DIM;
    float* szB  = statesZ + (size_t)b * (T + 1) * OUT_DIM;

    svB[o] = 0.f;
    szB[o] = 0.f;

    float v = 0.f, z = 0.f;
    int anySpike = 0;
    __syncthreads();

    float c0 = 0.f, c1 = 0.f, c2 = 0.f, c3 = 0.f;
    if (T > 0) c0 = curB[o];
    if (T > 1) c1 = curB[(size_t)OUT_DIM + o];
    if (T > 2) c2 = curB[(size_t)2 * OUT_DIM + o];
    if (T > 3) c3 = curB[(size_t)3 * OUT_DIM + o];

    int t = 0;
#pragma unroll 1
    for (; t + 3 < T; t += 4) {
        float n0 = (t + 4 < T) ? curB[(size_t)(t + 4) * OUT_DIM + o] : 0.f;
        lif_step(c0, v, z, anySpike, smask, o, wid, lane, d, omd, outB, svB, szB, t);
        float n1 = (t + 5 < T) ? curB[(size_t)(t + 5) * OUT_DIM + o] : 0.f;
        lif_step(c1, v, z, anySpike, smask, o, wid, lane, d, omd, outB, svB, szB, t + 1);
        float n2 = (t + 6 < T) ? curB[(size_t)(t + 6) * OUT_DIM + o] : 0.f;
        lif_step(c2, v, z, anySpike, smask, o, wid, lane, d, omd, outB, svB, szB, t + 2);
        float n3 = (t + 7 < T) ? curB[(size_t)(t + 7) * OUT_DIM + o] : 0.f;
        lif_step(c3, v, z, anySpike, smask, o, wid, lane, d, omd, outB, svB, szB, t + 3);
        c0 = n0; c1 = n1; c2 = n2; c3 = n3;
    }
    if (t < T) { lif_step(c0, v, z, anySpike, smask, o, wid, lane, d, omd, outB, svB, szB, t); t++; }
    if (t < T) { lif_step(c1, v, z, anySpike, smask, o, wid, lane, d, omd, outB, svB, szB, t); t++; }
    if (t < T) { lif_step(c2, v, z, anySpike, smask, o, wid, lane, d, omd, outB, svB, szB, t); t++; }
}

// ---------------------------------------------------------------------------
extern "C" void kernel_launch(void* const* d_in, const int* in_sizes, int n_in,
                              void* d_out, int out_size) {
    const float* x      = (const float*)d_in[0];  // [B, T, IN]
    const float* weight = (const float*)d_in[1];  // [OUT, IN]
    const float* bias   = (const float*)d_in[2];  // [OUT]
    const float* recur  = (const float*)d_in[3];  // [OUT, OUT]
    const float* decay  = (const float*)d_in[4];  // [OUT]

    const int OUT = in_sizes[2];                         // 512
    const int IN  = in_sizes[1] / OUT;                   // 512
    const long long M = (long long)in_sizes[0] / IN;     // B*T
    const long long B = (((long long)out_size / OUT) - 3 * M) / 2;
    const int T = (int)(M / B);
    const int NCH = (T + CH - 1) / CH;

    float* outputs = (float*)d_out;                        // [B,T,OUT]
    float* statesV = outputs + (size_t)B * T * OUT;        // [B,T+1,OUT]
    float* statesZ = statesV + (size_t)B * (T + 1) * OUT;  // [B,T+1,OUT]

    long long n4x = M * IN / 4;
    convert_x_kernel<<<(unsigned)((n4x + 255) / 256), 256>>>(x, n4x);
    convert_w_kernel<<<(OUT * IN / 4) / 256, 256>>>(weight);

    {
        dim3 grid(OUT / 32, OUT / 32), block(32, 32);
        transpose512_kernel<<<grid, block>>>(recur);
    }

    cudaFuncSetAttribute(gemm_hmma_kernel,
                         cudaFuncAttributeMaxDynamicSharedMemorySize, SMEM_GEMM);
    {
        float* cur;
        cudaGetSymbolAddress((void**)&cur, g_cur);
        dim3 grid((unsigned)(M / 128), OUT / 128);
        gemm_hmma_kernel<<<grid, 256, SMEM_GEMM>>>(bias, cur);
    }

    scan_s1_kernel<<<(unsigned)(B * NCH), OUT>>>(decay, T, NCH);
    scan_s2_kernel<<<(unsigned)B, OUT>>>(decay, T, NCH);
    scan_s3_kernel<<<(unsigned)(B * NCH), OUT>>>(decay, T, NCH,
                                                 outputs, statesV, statesZ);
    scan_s4_kernel<<<(unsigned)B, OUT>>>(decay, outputs, statesV, statesZ, T);
}

// round 10
// speedup vs baseline: 1.5237x; 1.0357x over previous
#include <cuda_runtime.h>
#include <cuda_bf16.h>
#include <cstdint>

// ---------------------------------------------------------------------------
// LIF layer forward (sm_103 base ISA):
//   cur = x @ W^T + bias   (3-pass split-bf16 HMMA GEMM; A split fused in-kernel)
//   scan: v = d*v*(1-z) + (1-d)*(cur_t + z @ R^T);  z = (v >= 1)
// Scan is chunk-parallelized on the no-spike linear path with an exact
// sequential fallback per batch element if any v >= THR (flagged).
// d_out = [outputs | statesV | statesZ]
// ---------------------------------------------------------------------------

#define IN_DIM  512
#define OUT_DIM 512
#define MAX_M   64000
#define MAX_B   128
#define CH      125
#define MAX_NCH 16

__device__ __nv_bfloat16 g_whi[(size_t)OUT_DIM * IN_DIM];
__device__ __nv_bfloat16 g_wlo[(size_t)OUT_DIM * IN_DIM];
__device__ float         g_RT [(size_t)OUT_DIM * OUT_DIM];
__device__ float         g_cur[(size_t)MAX_M * OUT_DIM];
__device__ float         g_csum  [(size_t)MAX_B * MAX_NCH * OUT_DIM];
__device__ float         g_vbound[(size_t)MAX_B * MAX_NCH * OUT_DIM];
__device__ int           g_flag[MAX_B];

// ======================= small prep kernels =================================
__global__ void convert_w_kernel(const float* __restrict__ w) {
    int i = blockIdx.x * blockDim.x + threadIdx.x;
    float4 v = ((const float4*)w)[i];
    float vv[4] = {v.x, v.y, v.z, v.w};
    __nv_bfloat16 h[4], l[4];
#pragma unroll
    for (int k = 0; k < 4; k++) {
        h[k] = __float2bfloat16_rn(vv[k]);
        l[k] = __float2bfloat16_rn(vv[k] - __bfloat162float(h[k]));
    }
    __nv_bfloat162* hi2 = (__nv_bfloat162*)g_whi;
    __nv_bfloat162* lo2 = (__nv_bfloat162*)g_wlo;
    hi2[i * 2]     = __halves2bfloat162(h[0], h[1]);
    hi2[i * 2 + 1] = __halves2bfloat162(h[2], h[3]);
    lo2[i * 2]     = __halves2bfloat162(l[0], l[1]);
    lo2[i * 2 + 1] = __halves2bfloat162(l[2], l[3]);
}

__global__ void transpose512_kernel(const float* __restrict__ R) {
    __shared__ float tile[32][33];
    int x = blockIdx.x * 32 + threadIdx.x;
    int y = blockIdx.y * 32 + threadIdx.y;
    tile[threadIdx.y][threadIdx.x] = R[y * OUT_DIM + x];
    __syncthreads();
    int xo = blockIdx.y * 32 + threadIdx.x;
    int yo = blockIdx.x * 32 + threadIdx.y;
    g_RT[yo * OUT_DIM + xo] = tile[threadIdx.x][threadIdx.y];
}

// ======================= HMMA GEMM ==========================================
// CTA 128x128, BK=64 (8 stages), double-buffered cp.async.
// A staged as fp32 (split to bf16 hi/lo in registers); B staged as bf16 hi/lo.
//   A part: 128 rows x 272 B (68 fp32, 16B-aligned rows)     = 34816 B
//   B part: 128 rows x 144 B (72 bf16)                       = 18432 B x2
#define A_STRIDE_F 68
#define A_PART_B   (128 * A_STRIDE_F * 4)       // 34816
#define B_STRIDE   72
#define B_PART_B   (128 * B_STRIDE * 2)         // 18432
#define STAGE_B    (A_PART_B + 2 * B_PART_B)    // 71680
#define SMEM_GEMM  (2 * STAGE_B)                // 143360

__device__ __forceinline__ void cp16(void* dst, const void* src) {
    uint32_t d;
    asm("{ .reg .u64 t; cvta.to.shared.u64 t, %1; cvt.u32.u64 %0, t; }"
        : "=r"(d) : "l"(dst));
    asm volatile("cp.async.cg.shared.global [%0], [%1], 16;" :: "r"(d), "l"(src));
}

__device__ __forceinline__ void mma_bf16(float* d, const uint32_t* a,
                                         const uint32_t* b) {
    asm volatile(
        "mma.sync.aligned.m16n8k16.row.col.f32.bf16.bf16.f32 "
        "{%0,%1,%2,%3}, {%4,%5,%6,%7}, {%8,%9}, {%0,%1,%2,%3};"
        : "+f"(d[0]), "+f"(d[1]), "+f"(d[2]), "+f"(d[3])
        : "r"(a[0]), "r"(a[1]), "r"(a[2]), "r"(a[3]), "r"(b[0]), "r"(b[1]));
}

// split two fp32 into (hi bf16x2, lo bf16x2); element 0 in low half.
__device__ __forceinline__ void split2(float2 f, uint32_t& h, uint32_t& l) {
    asm("cvt.rn.bf16x2.f32 %0, %1, %2;" : "=r"(h) : "f"(f.y), "f"(f.x));
    float h0 = __uint_as_float(h << 16);
    float h1 = __uint_as_float(h & 0xffff0000u);
    float l0 = f.x - h0;
    float l1 = f.y - h1;
    asm("cvt.rn.bf16x2.f32 %0, %1, %2;" : "=r"(l) : "f"(l1), "f"(l0));
}

__device__ __forceinline__ void load_stage(char* sm, int buf,
        const float* A, const __nv_bfloat16* Bh, const __nv_bfloat16* Bl,
        int k0, int tid) {
    char* base = sm + buf * STAGE_B;
    // A fp32: 2048 16B-chunks (128 rows x 16)
    {
        const float* gp = A + k0;
#pragma unroll
        for (int it = 0; it < 8; it++) {
            int chunk = it * 256 + tid;
            int row = chunk >> 4;
            int cc  = chunk & 15;
            cp16(base + row * (A_STRIDE_F * 4) + cc * 16,
                 gp + (size_t)row * IN_DIM + cc * 4);
        }
    }
    // B hi/lo: 1024 chunks each (128 rows x 8)
    const __nv_bfloat16* srcs[2] = {Bh, Bl};
#pragma unroll
    for (int p = 0; p < 2; p++) {
        char* pb = base + A_PART_B + p * B_PART_B;
        const __nv_bfloat16* gp = srcs[p] + k0;
#pragma unroll
        for (int it = 0; it < 4; it++) {
            int chunk = it * 256 + tid;
            int row = chunk >> 3;
            int cc  = chunk & 7;
            cp16(pb + row * (B_STRIDE * 2) + cc * 16,
                 gp + (size_t)row * IN_DIM + cc * 8);
        }
    }
    asm volatile("cp.async.commit_group;");
}

__global__ __launch_bounds__(256)
void gemm_hmma_kernel(const float* __restrict__ x,
                      const float* __restrict__ bias,
                      float* __restrict__ C) {
    extern __shared__ char sm[];
    const int tid  = threadIdx.x;
    const int wid  = tid >> 5;
    const int lane = tid & 31;
    const int g = lane >> 2, t = lane & 3;
    const int wm = wid >> 1;
    const int wn = wid & 1;
    const int m0 = blockIdx.x * 128;
    const int n0 = blockIdx.y * 128;

    const float*         A  = x      + (size_t)m0 * IN_DIM;
    const __nv_bfloat16* Bh = g_whi + (size_t)n0 * IN_DIM;
    const __nv_bfloat16* Bl = g_wlo + (size_t)n0 * IN_DIM;

    float d[2][8][4];
#pragma unroll
    for (int mi = 0; mi < 2; mi++)
#pragma unroll
        for (int nj = 0; nj < 8; nj++)
#pragma unroll
            for (int r = 0; r < 4; r++) d[mi][nj][r] = 0.f;

    load_stage(sm, 0, A, Bh, Bl, 0, tid);

#pragma unroll 1
    for (int s = 0; s < 8; s++) {
        if (s < 7) {
            load_stage(sm, (s + 1) & 1, A, Bh, Bl, (s + 1) * 64, tid);
            asm volatile("cp.async.wait_group 1;");
        } else {
            asm volatile("cp.async.wait_group 0;");
        }
        __syncthreads();

        const float*    Af  = (const float*)(sm + (s & 1) * STAGE_B);
        const uint32_t* Bs  = (const uint32_t*)(sm + (s & 1) * STAGE_B + A_PART_B);
        const uint32_t* Bls = Bs + B_PART_B / 4;
        const int HS = B_STRIDE / 2;

#pragma unroll
        for (int kk = 0; kk < 4; kk++) {
            const int col = kk * 16 + 2 * t;      // fp32 column of this lane
            uint32_t ah[2][4], al[2][4];
#pragma unroll
            for (int mi = 0; mi < 2; mi++) {
                int r0 = wm * 32 + mi * 16 + g;
                float2 f0 = *(const float2*)&Af[(size_t)r0 * A_STRIDE_F + col];
                float2 f1 = *(const float2*)&Af[(size_t)(r0 + 8) * A_STRIDE_F + col];
                float2 f2 = *(const float2*)&Af[(size_t)r0 * A_STRIDE_F + col + 8];
                float2 f3 = *(const float2*)&Af[(size_t)(r0 + 8) * A_STRIDE_F + col + 8];
                split2(f0, ah[mi][0], al[mi][0]);
                split2(f1, ah[mi][1], al[mi][1]);
                split2(f2, ah[mi][2], al[mi][2]);
                split2(f3, ah[mi][3], al[mi][3]);
            }
            uint32_t bh[8][2], bl[8][2];
#pragma unroll
            for (int nj = 0; nj < 8; nj++) {
                int rn = wn * 64 + nj * 8 + g;
                int cb = kk * 8 + t;
                bh[nj][0] = Bs [rn * HS + cb];
                bh[nj][1] = Bs [rn * HS + cb + 4];
                bl[nj][0] = Bls[rn * HS + cb];
                bl[nj][1] = Bls[rn * HS + cb + 4];
            }
#pragma unroll
            for (int mi = 0; mi < 2; mi++)
#pragma unroll
                for (int nj = 0; nj < 8; nj++) {
                    mma_bf16(d[mi][nj], ah[mi], bh[nj]);
                    mma_bf16(d[mi][nj], ah[mi], bl[nj]);
                    mma_bf16(d[mi][nj], al[mi], bh[nj]);
                }
        }
        __syncthreads();
    }

#pragma unroll
    for (int nj = 0; nj < 8; nj++) {
        int cc = n0 + wn * 64 + nj * 8 + 2 * t;
        float2 bv = *(const float2*)&bias[cc];
#pragma unroll
        for (int mi = 0; mi < 2; mi++) {
            int r0 = m0 + wm * 32 + mi * 16 + g;
            float2 o0 = {d[mi][nj][0] + bv.x, d[mi][nj][1] + bv.y};
            float2 o1 = {d[mi][nj][2] + bv.x, d[mi][nj][3] + bv.y};
            *(float2*)&C[(size_t)r0 * OUT_DIM + cc]       = o0;
            *(float2*)&C[(size_t)(r0 + 8) * OUT_DIM + cc] = o1;
        }
    }
}

// ================= Parallel scan, stage 1: chunk-local EMA sums ==============
__global__ __launch_bounds__(OUT_DIM)
void scan_s1_kernel(const float* __restrict__ decay, int T, int NCH) {
    const int bc = blockIdx.x;
    const int b  = bc / NCH;
    const int ch = bc % NCH;
    const int o  = threadIdx.x;
    if (ch == 0 && o == 0) g_flag[b] = 0;

    const float d = decay[o];
    const float omd = 1.f - d;
    const int t0 = ch * CH;
    const int t1 = min(T, t0 + CH);
    const float* curB = g_cur + ((size_t)b * T + t0) * OUT_DIM + o;

    float s = 0.f;
#pragma unroll 1
    for (int t = t0; t < t1; t++) {
        s = d * s + omd * (*curB);
        curB += OUT_DIM;
    }
    g_csum[(size_t)bc * OUT_DIM + o] = s;
}

// ================= stage 2: combine chunk boundaries ========================
__global__ __launch_bounds__(OUT_DIM)
void scan_s2_kernel(const float* __restrict__ decay, int T, int NCH) {
    const int b = blockIdx.x;
    const int o = threadIdx.x;
    const float d = decay[o];

    float dpCH = 1.f;
#pragma unroll 1
    for (int i = 0; i < CH; i++) dpCH *= d;

    float vb = 0.f;
#pragma unroll 1
    for (int ch = 0; ch < NCH; ch++) {
        g_vbound[((size_t)b * NCH + ch) * OUT_DIM + o] = vb;
        int len = min(CH, T - ch * CH);
        float dp = dpCH;
        if (len != CH) { dp = 1.f; for (int i = 0; i < len; i++) dp *= d; }
        vb = dp * vb + g_csum[((size_t)b * NCH + ch) * OUT_DIM + o];
    }
}

// ================= stage 3: expand no-spike trajectory + flag ================
__global__ __launch_bounds__(OUT_DIM)
void scan_s3_kernel(const float* __restrict__ decay, int T, int NCH,
                    float* __restrict__ outputs,
                    float* __restrict__ statesV,
                    float* __restrict__ statesZ) {
    const int bc = blockIdx.x;
    const int b  = bc / NCH;
    const int ch = bc % NCH;
    const int o  = threadIdx.x;

    const float d = decay[o];
    const float omd = 1.f - d;
    const int t0 = ch * CH;
    const int t1 = min(T, t0 + CH);

    const float* curB = g_cur + ((size_t)b * T + t0) * OUT_DIM + o;
    float* outB = outputs + ((size_t)b * T + t0) * OUT_DIM + o;
    float* svB  = statesV + ((size_t)b * (T + 1) + t0 + 1) * OUT_DIM + o;
    float* szB  = statesZ + ((size_t)b * (T + 1) + t0 + 1) * OUT_DIM + o;

    if (ch == 0) {
        statesV[((size_t)b * (T + 1)) * OUT_DIM + o] = 0.f;
        statesZ[((size_t)b * (T + 1)) * OUT_DIM + o] = 0.f;
    }

    float v = g_vbound[(size_t)bc * OUT_DIM + o];
    bool spike = false;
#pragma unroll 1
    for (int t = t0; t < t1; t++) {
        v = d * v + omd * (*curB);
        float z = (v >= 1.f) ? 1.f : 0.f;
        spike |= (z > 0.f);
        *outB = z;  *svB = v;  *szB = z;
        curB += OUT_DIM; outB += OUT_DIM; svB += OUT_DIM; szB += OUT_DIM;
    }
    if (__syncthreads_or(spike)) {
        if (o == 0) atomicOr(&g_flag[b], 1);
    }
}

// ================= stage 4: exact sequential fallback (flagged only) ========
__device__ __forceinline__ void lif_step(
    float c, float& v, float& z, int& anySpike,
    unsigned* smask, int o, int wid, int lane,
    float d, float omd,
    float* __restrict__ outB, float* __restrict__ svB, float* __restrict__ szB,
    int t)
{
    float soma = c;
    if (anySpike) {
#pragma unroll 1
        for (int w = 0; w < OUT_DIM / 32; w++) {
            unsigned m = smask[w];
            while (m) {
                int j = w * 32 + (__ffs(m) - 1);
                m &= (m - 1);
                soma += g_RT[(size_t)j * OUT_DIM + o];
            }
        }
    }
    v = d * (v * (1.f - z)) + omd * soma;
    z = (v >= 1.f) ? 1.f : 0.f;
    outB[(size_t)t * OUT_DIM + o]      = z;
    svB[(size_t)(t + 1) * OUT_DIM + o] = v;
    szB[(size_t)(t + 1) * OUT_DIM + o] = z;
    unsigned bal = __ballot_sync(0xffffffffu, z > 0.f);
    anySpike = __syncthreads_count(z > 0.f);
    if (anySpike) {
        if (lane == 0) smask[wid] = bal;
        __syncthreads();
    }
}

__global__ __launch_bounds__(OUT_DIM, 1)
void scan_s4_kernel(const float* __restrict__ decay,
                    float* __restrict__ outputs,
                    float* __restrict__ statesV,
                    float* __restrict__ statesZ,
                    int T) {
    const int b = blockIdx.x;
    if (g_flag[b] == 0) return;
    const int o = threadIdx.x;
    const int wid = o >> 5, lane = o & 31;

    __shared__ unsigned smask[OUT_DIM / 32];
    if (o < OUT_DIM / 32) smask[o] = 0u;

    const float d   = decay[o];
    const float omd = 1.f - d;

    const float* curB = g_cur + (size_t)b * T * OUT_DIM;
    float* outB = outputs + (size_t)b * T * OUT_DIM;
    float* svB  = statesV + (size_t)b * (T + 1) * OUT_DIM;
    float* szB  = statesZ + (size_t)b * (T + 1) * OUT_DIM;

    svB[o] = 0.f;
    szB[o] = 0.f;

    float v = 0.f, z = 0.f;
    int anySpike = 0;
    __syncthreads();

    float c0 = 0.f, c1 = 0.f, c2 = 0.f, c3 = 0.f;
    if (T > 0) c0 = curB[o];
    if (T > 1) c1 = curB[(size_t)OUT_DIM + o];
    if (T > 2) c2 = curB[(size_t)2 * OUT_DIM + o];
    if (T > 3) c3 = curB[(size_t)3 * OUT_DIM + o];

    int t = 0;
#pragma unroll 1
    for (; t + 3 < T; t += 4) {
        float n0 = (t + 4 < T) ? curB[(size_t)(t + 4) * OUT_DIM + o] : 0.f;
        lif_step(c0, v, z, anySpike, smask, o, wid, lane, d, omd, outB, svB, szB, t);
        float n1 = (t + 5 < T) ? curB[(size_t)(t + 5) * OUT_DIM + o] : 0.f;
        lif_step(c1, v, z, anySpike, smask, o, wid, lane, d, omd, outB, svB, szB, t + 1);
        float n2 = (t + 6 < T) ? curB[(size_t)(t + 6) * OUT_DIM + o] : 0.f;
        lif_step(c2, v, z, anySpike, smask, o, wid, lane, d, omd, outB, svB, szB, t + 2);
        float n3 = (t + 7 < T) ? curB[(size_t)(t + 7) * OUT_DIM + o] : 0.f;
        lif_step(c3, v, z, anySpike, smask, o, wid, lane, d, omd, outB, svB, szB, t + 3);
        c0 = n0; c1 = n1; c2 = n2; c3 = n3;
    }
    if (t < T) { lif_step(c0, v, z, anySpike, smask, o, wid, lane, d, omd, outB, svB, szB, t); t++; }
    if (t < T) { lif_step(c1, v, z, anySpike, smask, o, wid, lane, d, omd, outB, svB, szB, t); t++; }
    if (t < T) { lif_step(c2, v, z, anySpike, smask, o, wid, lane, d, omd, outB, svB, szB, t); t++; }
}

// ---------------------------------------------------------------------------
extern "C" void kernel_launch(void* const* d_in, const int* in_sizes, int n_in,
                              void* d_out, int out_size) {
    const float* x      = (const float*)d_in[0];  // [B, T, IN]
    const float* weight = (const float*)d_in[1];  // [OUT, IN]
    const float* bias   = (const float*)d_in[2];  // [OUT]
    const float* recur  = (const float*)d_in[3];  // [OUT, OUT]
    const float* decay  = (const float*)d_in[4];  // [OUT]

    const int OUT = in_sizes[2];                         // 512
    const int IN  = in_sizes[1] / OUT;                   // 512
    const long long M = (long long)in_sizes[0] / IN;     // B*T
    const long long B = (((long long)out_size / OUT) - 3 * M) / 2;
    const int T = (int)(M / B);
    const int NCH = (T + CH - 1) / CH;

    float* outputs = (float*)d_out;                        // [B,T,OUT]
    float* statesV = outputs + (size_t)B * T * OUT;        // [B,T+1,OUT]
    float* statesZ = statesV + (size_t)B * (T + 1) * OUT;  // [B,T+1,OUT]

    convert_w_kernel<<<(OUT * IN / 4) / 256, 256>>>(weight);

    {
        dim3 grid(OUT / 32, OUT / 32), block(32, 32);
        transpose512_kernel<<<grid, block>>>(recur);
    }

    cudaFuncSetAttribute(gemm_hmma_kernel,
                         cudaFuncAttributeMaxDynamicSharedMemorySize, SMEM_GEMM);
    {
        float* cur;
        cudaGetSymbolAddress((void**)&cur, g_cur);
        dim3 grid((unsigned)(M / 128), OUT / 128);
        gemm_hmma_kernel<<<grid, 256, SMEM_GEMM>>>(x, bias, cur);
    }

    scan_s1_kernel<<<(unsigned)(B * NCH), OUT>>>(decay, T, NCH);
    scan_s2_kernel<<<(unsigned)B, OUT>>>(decay, T, NCH);
    scan_s3_kernel<<<(unsigned)(B * NCH), OUT>>>(decay, T, NCH,
                                                 outputs, statesV, statesZ);
    scan_s4_kernel<<<(unsigned)B, OUT>>>(decay, outputs, statesV, statesZ, T);
}

// round 11
// speedup vs baseline: 1.5635x; 1.0261x over previous
#include <cuda_runtime.h>
#include <cuda_bf16.h>
#include <cstdint>

// ---------------------------------------------------------------------------
// LIF layer forward (sm_103 base ISA):
//   cur = x @ W^T + bias   (3-pass split-bf16 HMMA GEMM; A split fused in-kernel,
//                           B fragments via ldmatrix.x4)
//   scan: v = d*v*(1-z) + (1-d)*(cur_t + z @ R^T);  z = (v >= 1)
// Scan chunk-parallelized on the no-spike linear path + exact sequential
// fallback per batch element if any v >= THR (flagged).
// d_out = [outputs | statesV | statesZ]
// ---------------------------------------------------------------------------

#define IN_DIM  512
#define OUT_DIM 512
#define MAX_M   64000
#define MAX_B   128
#define CH      125
#define MAX_NCH 16

__device__ __nv_bfloat16 g_whi[(size_t)OUT_DIM * IN_DIM];
__device__ __nv_bfloat16 g_wlo[(size_t)OUT_DIM * IN_DIM];
__device__ float         g_RT [(size_t)OUT_DIM * OUT_DIM];
__device__ float         g_cur[(size_t)MAX_M * OUT_DIM];
__device__ float         g_csum  [(size_t)MAX_B * MAX_NCH * OUT_DIM];
__device__ float         g_vbound[(size_t)MAX_B * MAX_NCH * OUT_DIM];
__device__ int           g_flag[MAX_B];

// ======================= small prep kernels =================================
__global__ void convert_w_kernel(const float* __restrict__ w) {
    int i = blockIdx.x * blockDim.x + threadIdx.x;
    float4 v = ((const float4*)w)[i];
    float vv[4] = {v.x, v.y, v.z, v.w};
    __nv_bfloat16 h[4], l[4];
#pragma unroll
    for (int k = 0; k < 4; k++) {
        h[k] = __float2bfloat16_rn(vv[k]);
        l[k] = __float2bfloat16_rn(vv[k] - __bfloat162float(h[k]));
    }
    __nv_bfloat162* hi2 = (__nv_bfloat162*)g_whi;
    __nv_bfloat162* lo2 = (__nv_bfloat162*)g_wlo;
    hi2[i * 2]     = __halves2bfloat162(h[0], h[1]);
    hi2[i * 2 + 1] = __halves2bfloat162(h[2], h[3]);
    lo2[i * 2]     = __halves2bfloat162(l[0], l[1]);
    lo2[i * 2 + 1] = __halves2bfloat162(l[2], l[3]);
}

__global__ void transpose512_kernel(const float* __restrict__ R) {
    __shared__ float tile[32][33];
    int x = blockIdx.x * 32 + threadIdx.x;
    int y = blockIdx.y * 32 + threadIdx.y;
    tile[threadIdx.y][threadIdx.x] = R[y * OUT_DIM + x];
    __syncthreads();
    int xo = blockIdx.y * 32 + threadIdx.x;
    int yo = blockIdx.x * 32 + threadIdx.y;
    g_RT[yo * OUT_DIM + xo] = tile[threadIdx.x][threadIdx.y];
}

// ======================= HMMA GEMM ==========================================
// CTA 128x128, BK=64 (8 stages), double-buffered cp.async.
// A staged fp32 (register hi/lo split); B staged bf16 hi/lo, ldmatrix feeds.
#define A_STRIDE_F 68
#define A_PART_B   (128 * A_STRIDE_F * 4)       // 34816
#define B_STRIDE   72
#define B_ROW_B    (B_STRIDE * 2)               // 144
#define B_PART_B   (128 * B_ROW_B)              // 18432
#define STAGE_B    (A_PART_B + 2 * B_PART_B)    // 71680
#define SMEM_GEMM  (2 * STAGE_B)                // 143360

__device__ __forceinline__ uint32_t smem_u32(const void* p) {
    uint32_t a;
    asm("{ .reg .u64 t; cvta.to.shared.u64 t, %1; cvt.u32.u64 %0, t; }"
        : "=r"(a) : "l"(p));
    return a;
}

__device__ __forceinline__ void cp16(void* dst, const void* src) {
    uint32_t d;
    asm("{ .reg .u64 t; cvta.to.shared.u64 t, %1; cvt.u32.u64 %0, t; }"
        : "=r"(d) : "l"(dst));
    asm volatile("cp.async.cg.shared.global [%0], [%1], 16;" :: "r"(d), "l"(src));
}

__device__ __forceinline__ void ldsm_x4(uint32_t* r, uint32_t addr) {
    asm volatile("ldmatrix.sync.aligned.m8n8.x4.shared.b16 {%0,%1,%2,%3}, [%4];"
        : "=r"(r[0]), "=r"(r[1]), "=r"(r[2]), "=r"(r[3]) : "r"(addr));
}

__device__ __forceinline__ void mma_bf16(float* d, const uint32_t* a,
                                         uint32_t b0, uint32_t b1) {
    asm volatile(
        "mma.sync.aligned.m16n8k16.row.col.f32.bf16.bf16.f32 "
        "{%0,%1,%2,%3}, {%4,%5,%6,%7}, {%8,%9}, {%0,%1,%2,%3};"
        : "+f"(d[0]), "+f"(d[1]), "+f"(d[2]), "+f"(d[3])
        : "r"(a[0]), "r"(a[1]), "r"(a[2]), "r"(a[3]), "r"(b0), "r"(b1));
}

// split two fp32 into (hi bf16x2, lo bf16x2); element 0 in low half.
__device__ __forceinline__ void split2(float2 f, uint32_t& h, uint32_t& l) {
    asm("cvt.rn.bf16x2.f32 %0, %1, %2;" : "=r"(h) : "f"(f.y), "f"(f.x));
    float h0 = __uint_as_float(h << 16);
    float h1 = __uint_as_float(h & 0xffff0000u);
    float l0 = f.x - h0;
    float l1 = f.y - h1;
    asm("cvt.rn.bf16x2.f32 %0, %1, %2;" : "=r"(l) : "f"(l1), "f"(l0));
}

__device__ __forceinline__ void load_stage(char* sm, int buf,
        const float* A, const __nv_bfloat16* Bh, const __nv_bfloat16* Bl,
        int k0, int tid) {
    char* base = sm + buf * STAGE_B;
    {
        const float* gp = A + k0;
#pragma unroll
        for (int it = 0; it < 8; it++) {
            int chunk = it * 256 + tid;
            int row = chunk >> 4;
            int cc  = chunk & 15;
            cp16(base + row * (A_STRIDE_F * 4) + cc * 16,
                 gp + (size_t)row * IN_DIM + cc * 4);
        }
    }
    const __nv_bfloat16* srcs[2] = {Bh, Bl};
#pragma unroll
    for (int p = 0; p < 2; p++) {
        char* pb = base + A_PART_B + p * B_PART_B;
        const __nv_bfloat16* gp = srcs[p] + k0;
#pragma unroll
        for (int it = 0; it < 4; it++) {
            int chunk = it * 256 + tid;
            int row = chunk >> 3;
            int cc  = chunk & 7;
            cp16(pb + row * B_ROW_B + cc * 16,
                 gp + (size_t)row * IN_DIM + cc * 8);
        }
    }
    asm volatile("cp.async.commit_group;");
}

__global__ __launch_bounds__(256)
void gemm_hmma_kernel(const float* __restrict__ x,
                      const float* __restrict__ bias,
                      float* __restrict__ C) {
    extern __shared__ char sm[];
    const uint32_t sbase = smem_u32(sm);
    const int tid  = threadIdx.x;
    const int wid  = tid >> 5;
    const int lane = tid & 31;
    const int g = lane >> 2, t = lane & 3;
    const int wm = wid >> 1;
    const int wn = wid & 1;
    const int m0 = blockIdx.x * 128;
    const int n0 = blockIdx.y * 128;

    const float*         A  = x     + (size_t)m0 * IN_DIM;
    const __nv_bfloat16* Bh = g_whi + (size_t)n0 * IN_DIM;
    const __nv_bfloat16* Bl = g_wlo + (size_t)n0 * IN_DIM;

    // ldmatrix lane address offset within B part (16 rows x 2 k-halves)
    const uint32_t bRowOff = (uint32_t)(wn * 64 + (lane & 15)) * B_ROW_B
                           + (uint32_t)(lane >> 4) * 16;

    float d[2][8][4];
#pragma unroll
    for (int mi = 0; mi < 2; mi++)
#pragma unroll
        for (int nj = 0; nj < 8; nj++)
#pragma unroll
            for (int r = 0; r < 4; r++) d[mi][nj][r] = 0.f;

    load_stage(sm, 0, A, Bh, Bl, 0, tid);

#pragma unroll 1
    for (int s = 0; s < 8; s++) {
        if (s < 7) {
            load_stage(sm, (s + 1) & 1, A, Bh, Bl, (s + 1) * 64, tid);
            asm volatile("cp.async.wait_group 1;");
        } else {
            asm volatile("cp.async.wait_group 0;");
        }
        __syncthreads();

        const float* Af = (const float*)(sm + (s & 1) * STAGE_B);
        const uint32_t bHb = sbase + (s & 1) * STAGE_B + A_PART_B + bRowOff;
        const uint32_t bLb = bHb + B_PART_B;

#pragma unroll
        for (int kk = 0; kk < 4; kk++) {
            const int col = kk * 16 + 2 * t;
            uint32_t ah[2][4], al[2][4];
#pragma unroll
            for (int mi = 0; mi < 2; mi++) {
                int r0 = wm * 32 + mi * 16 + g;
                float2 f0 = *(const float2*)&Af[(size_t)r0 * A_STRIDE_F + col];
                float2 f1 = *(const float2*)&Af[(size_t)(r0 + 8) * A_STRIDE_F + col];
                float2 f2 = *(const float2*)&Af[(size_t)r0 * A_STRIDE_F + col + 8];
                float2 f3 = *(const float2*)&Af[(size_t)(r0 + 8) * A_STRIDE_F + col + 8];
                split2(f0, ah[mi][0], al[mi][0]);
                split2(f1, ah[mi][1], al[mi][1]);
                split2(f2, ah[mi][2], al[mi][2]);
                split2(f3, ah[mi][3], al[mi][3]);
            }
            // B fragments: 8 ldmatrix.x4 (4 n-blocks x {hi,lo})
            uint32_t bh[8][2], bl[8][2];
#pragma unroll
            for (int p = 0; p < 4; p++) {
                uint32_t r[4];
                ldsm_x4(r, bHb + p * (16 * B_ROW_B) + kk * 32);
                bh[2 * p][0] = r[0]; bh[2 * p + 1][0] = r[1];
                bh[2 * p][1] = r[2]; bh[2 * p + 1][1] = r[3];
                ldsm_x4(r, bLb + p * (16 * B_ROW_B) + kk * 32);
                bl[2 * p][0] = r[0]; bl[2 * p + 1][0] = r[1];
                bl[2 * p][1] = r[2]; bl[2 * p + 1][1] = r[3];
            }
            // pass-major: consecutive MMAs never share an accumulator
#pragma unroll
            for (int mi = 0; mi < 2; mi++)
#pragma unroll
                for (int nj = 0; nj < 8; nj++)
                    mma_bf16(d[mi][nj], ah[mi], bh[nj][0], bh[nj][1]);
#pragma unroll
            for (int mi = 0; mi < 2; mi++)
#pragma unroll
                for (int nj = 0; nj < 8; nj++)
                    mma_bf16(d[mi][nj], ah[mi], bl[nj][0], bl[nj][1]);
#pragma unroll
            for (int mi = 0; mi < 2; mi++)
#pragma unroll
                for (int nj = 0; nj < 8; nj++)
                    mma_bf16(d[mi][nj], al[mi], bh[nj][0], bh[nj][1]);
        }
        __syncthreads();
    }

#pragma unroll
    for (int nj = 0; nj < 8; nj++) {
        int cc = n0 + wn * 64 + nj * 8 + 2 * t;
        float2 bv = *(const float2*)&bias[cc];
#pragma unroll
        for (int mi = 0; mi < 2; mi++) {
            int r0 = m0 + wm * 32 + mi * 16 + g;
            float2 o0 = {d[mi][nj][0] + bv.x, d[mi][nj][1] + bv.y};
            float2 o1 = {d[mi][nj][2] + bv.x, d[mi][nj][3] + bv.y};
            *(float2*)&C[(size_t)r0 * OUT_DIM + cc]       = o0;
            *(float2*)&C[(size_t)(r0 + 8) * OUT_DIM + cc] = o1;
        }
    }
}

// ================= Parallel scan, stage 1: chunk-local EMA sums ==============
// 4-deep load ring: MLP=4 hides DRAM latency behind the serial EMA chain.
__global__ __launch_bounds__(OUT_DIM)
void scan_s1_kernel(const float* __restrict__ decay, int T, int NCH) {
    const int bc = blockIdx.x;
    const int b  = bc / NCH;
    const int ch = bc % NCH;
    const int o  = threadIdx.x;
    if (ch == 0 && o == 0) g_flag[b] = 0;

    const float d = decay[o];
    const float omd = 1.f - d;
    const int t0 = ch * CH;
    const int len = min(T - t0, CH);
    const float* curB = g_cur + ((size_t)b * T + t0) * OUT_DIM + o;

    float c0 = 0.f, c1 = 0.f, c2 = 0.f, c3 = 0.f;
    if (len > 0) c0 = curB[0];
    if (len > 1) c1 = curB[(size_t)OUT_DIM];
    if (len > 2) c2 = curB[(size_t)2 * OUT_DIM];
    if (len > 3) c3 = curB[(size_t)3 * OUT_DIM];

    float s = 0.f;
    int t = 0;
#pragma unroll 1
    for (; t + 4 <= len; t += 4) {
        float n0 = (t + 4 < len) ? curB[(size_t)(t + 4) * OUT_DIM] : 0.f;
        float n1 = (t + 5 < len) ? curB[(size_t)(t + 5) * OUT_DIM] : 0.f;
        float n2 = (t + 6 < len) ? curB[(size_t)(t + 6) * OUT_DIM] : 0.f;
        float n3 = (t + 7 < len) ? curB[(size_t)(t + 7) * OUT_DIM] : 0.f;
        s = d * s + omd * c0;
        s = d * s + omd * c1;
        s = d * s + omd * c2;
        s = d * s + omd * c3;
        c0 = n0; c1 = n1; c2 = n2; c3 = n3;
    }
    if (t < len) { s = d * s + omd * c0; t++; }
    if (t < len) { s = d * s + omd * c1; t++; }
    if (t < len) { s = d * s + omd * c2; t++; }

    g_csum[(size_t)bc * OUT_DIM + o] = s;
}

// ================= stage 2: combine chunk boundaries ========================
__global__ __launch_bounds__(OUT_DIM)
void scan_s2_kernel(const float* __restrict__ decay, int T, int NCH) {
    const int b = blockIdx.x;
    const int o = threadIdx.x;
    const float d = decay[o];

    float dpCH = 1.f;
#pragma unroll 1
    for (int i = 0; i < CH; i++) dpCH *= d;

    float vb = 0.f;
#pragma unroll 1
    for (int ch = 0; ch < NCH; ch++) {
        g_vbound[((size_t)b * NCH + ch) * OUT_DIM + o] = vb;
        int len = min(CH, T - ch * CH);
        float dp = dpCH;
        if (len != CH) { dp = 1.f; for (int i = 0; i < len; i++) dp *= d; }
        vb = dp * vb + g_csum[((size_t)b * NCH + ch) * OUT_DIM + o];
    }
}

// ================= stage 3: expand no-spike trajectory + flag ================
__global__ __launch_bounds__(OUT_DIM)
void scan_s3_kernel(const float* __restrict__ decay, int T, int NCH,
                    float* __restrict__ outputs,
                    float* __restrict__ statesV,
                    float* __restrict__ statesZ) {
    const int bc = blockIdx.x;
    const int b  = bc / NCH;
    const int ch = bc % NCH;
    const int o  = threadIdx.x;

    const float d = decay[o];
    const float omd = 1.f - d;
    const int t0 = ch * CH;
    const int len = min(T - t0, CH);

    const float* curB = g_cur + ((size_t)b * T + t0) * OUT_DIM + o;
    float* outB = outputs + ((size_t)b * T + t0) * OUT_DIM + o;
    float* svB  = statesV + ((size_t)b * (T + 1) + t0 + 1) * OUT_DIM + o;
    float* szB  = statesZ + ((size_t)b * (T + 1) + t0 + 1) * OUT_DIM + o;

    if (ch == 0) {
        statesV[((size_t)b * (T + 1)) * OUT_DIM + o] = 0.f;
        statesZ[((size_t)b * (T + 1)) * OUT_DIM + o] = 0.f;
    }

    float c0 = 0.f, c1 = 0.f, c2 = 0.f, c3 = 0.f;
    if (len > 0) c0 = curB[0];
    if (len > 1) c1 = curB[(size_t)OUT_DIM];
    if (len > 2) c2 = curB[(size_t)2 * OUT_DIM];
    if (len > 3) c3 = curB[(size_t)3 * OUT_DIM];

    float v = g_vbound[(size_t)bc * OUT_DIM + o];
    bool spike = false;
    int t = 0;
#pragma unroll 1
    for (; t + 4 <= len; t += 4) {
        float n0 = (t + 4 < len) ? curB[(size_t)(t + 4) * OUT_DIM] : 0.f;
        float n1 = (t + 5 < len) ? curB[(size_t)(t + 5) * OUT_DIM] : 0.f;
        float n2 = (t + 6 < len) ? curB[(size_t)(t + 6) * OUT_DIM] : 0.f;
        float n3 = (t + 7 < len) ? curB[(size_t)(t + 7) * OUT_DIM] : 0.f;
#pragma unroll
        for (int u = 0; u < 4; u++) {
            float cc = (u == 0) ? c0 : (u == 1) ? c1 : (u == 2) ? c2 : c3;
            v = d * v + omd * cc;
            float z = (v >= 1.f) ? 1.f : 0.f;
            spike |= (z > 0.f);
            size_t off = (size_t)(t + u) * OUT_DIM;
            outB[off] = z; svB[off] = v; szB[off] = z;
        }
        c0 = n0; c1 = n1; c2 = n2; c3 = n3;
    }
#pragma unroll 1
    for (int u = 0; t < len; t++, u++) {
        float cc = (u == 0) ? c0 : (u == 1) ? c1 : c2;
        v = d * v + omd * cc;
        float z = (v >= 1.f) ? 1.f : 0.f;
        spike |= (z > 0.f);
        size_t off = (size_t)t * OUT_DIM;
        outB[off] = z; svB[off] = v; szB[off] = z;
    }
    if (__syncthreads_or(spike)) {
        if (o == 0) atomicOr(&g_flag[b], 1);
    }
}

// ================= stage 4: exact sequential fallback (flagged only) ========
__device__ __forceinline__ void lif_step(
    float c, float& v, float& z, int& anySpike,
    unsigned* smask, int o, int wid, int lane,
    float d, float omd,
    float* __restrict__ outB, float* __restrict__ svB, float* __restrict__ szB,
    int t)
{
    float soma = c;
    if (anySpike) {
#pragma unroll 1
        for (int w = 0; w < OUT_DIM / 32; w++) {
            unsigned m = smask[w];
            while (m) {
                int j = w * 32 + (__ffs(m) - 1);
                m &= (m - 1);
                soma += g_RT[(size_t)j * OUT_DIM + o];
            }
        }
    }
    v = d * (v * (1.f - z)) + omd * soma;
    z = (v >= 1.f) ? 1.f : 0.f;
    outB[(size_t)t * OUT_DIM + o]      = z;
    svB[(size_t)(t + 1) * OUT_DIM + o] = v;
    szB[(size_t)(t + 1) * OUT_DIM + o] = z;
    unsigned bal = __ballot_sync(0xffffffffu, z > 0.f);
    anySpike = __syncthreads_count(z > 0.f);
    if (anySpike) {
        if (lane == 0) smask[wid] = bal;
        __syncthreads();
    }
}

__global__ __launch_bounds__(OUT_DIM, 1)
void scan_s4_kernel(const float* __restrict__ decay,
                    float* __restrict__ outputs,
                    float* __restrict__ statesV,
                    float* __restrict__ statesZ,
                    int T) {
    const int b = blockIdx.x;
    if (g_flag[b] == 0) return;
    const int o = threadIdx.x;
    const int wid = o >> 5, lane = o & 31;

    __shared__ unsigned smask[OUT_DIM / 32];
    if (o < OUT_DIM / 32) smask[o] = 0u;

    const float d   = decay[o];
    const float omd = 1.f - d;

    const float* curB = g_cur + (size_t)b * T * OUT_DIM;
    float* outB = outputs + (size_t)b * T * OUT_DIM;
    float* svB  = statesV + (size_t)b * (T + 1) * OUT_DIM;
    float* szB  = statesZ + (size_t)b * (T + 1) * OUT_DIM;

    svB[o] = 0.f;
    szB[o] = 0.f;

    float v = 0.f, z = 0.f;
    int anySpike = 0;
    __syncthreads();

    float c0 = 0.f, c1 = 0.f, c2 = 0.f, c3 = 0.f;
    if (T > 0) c0 = curB[o];
    if (T > 1) c1 = curB[(size_t)OUT_DIM + o];
    if (T > 2) c2 = curB[(size_t)2 * OUT_DIM + o];
    if (T > 3) c3 = curB[(size_t)3 * OUT_DIM + o];

    int t = 0;
#pragma unroll 1
    for (; t + 3 < T; t += 4) {
        float n0 = (t + 4 < T) ? curB[(size_t)(t + 4) * OUT_DIM + o] : 0.f;
        lif_step(c0, v, z, anySpike, smask, o, wid, lane, d, omd, outB, svB, szB, t);
        float n1 = (t + 5 < T) ? curB[(size_t)(t + 5) * OUT_DIM + o] : 0.f;
        lif_step(c1, v, z, anySpike, smask, o, wid, lane, d, omd, outB, svB, szB, t + 1);
        float n2 = (t + 6 < T) ? curB[(size_t)(t + 6) * OUT_DIM + o] : 0.f;
        lif_step(c2, v, z, anySpike, smask, o, wid, lane, d, omd, outB, svB, szB, t + 2);
        float n3 = (t + 7 < T) ? curB[(size_t)(t + 7) * OUT_DIM + o] : 0.f;
        lif_step(c3, v, z, anySpike, smask, o, wid, lane, d, omd, outB, svB, szB, t + 3);
        c0 = n0; c1 = n1; c2 = n2; c3 = n3;
    }
    if (t < T) { lif_step(c0, v, z, anySpike, smask, o, wid, lane, d, omd, outB, svB, szB, t); t++; }
    if (t < T) { lif_step(c1, v, z, anySpike, smask, o, wid, lane, d, omd, outB, svB, szB, t); t++; }
    if (t < T) { lif_step(c2, v, z, anySpike, smask, o, wid, lane, d, omd, outB, svB, szB, t); t++; }
}

// ---------------------------------------------------------------------------
extern "C" void kernel_launch(void* const* d_in, const int* in_sizes, int n_in,
                              void* d_out, int out_size) {
    const float* x      = (const float*)d_in[0];  // [B, T, IN]
    const float* weight = (const float*)d_in[1];  // [OUT, IN]
    const float* bias   = (const float*)d_in[2];  // [OUT]
    const float* recur  = (const float*)d_in[3];  // [OUT, OUT]
    const float* decay  = (const float*)d_in[4];  // [OUT]

    const int OUT = in_sizes[2];                         // 512
    const int IN  = in_sizes[1] / OUT;                   // 512
    const long long M = (long long)in_sizes[0] / IN;     // B*T
    const long long B = (((long long)out_size / OUT) - 3 * M) / 2;
    const int T = (int)(M / B);
    const int NCH = (T + CH - 1) / CH;

    float* outputs = (float*)d_out;                        // [B,T,OUT]
    float* statesV = outputs + (size_t)B * T * OUT;        // [B,T+1,OUT]
    float* statesZ = statesV + (size_t)B * (T + 1) * OUT;  // [B,T+1,OUT]

    convert_w_kernel<<<(OUT * IN / 4) / 256, 256>>>(weight);

    {
        dim3 grid(OUT / 32, OUT / 32), block(32, 32);
        transpose512_kernel<<<grid, block>>>(recur);
    }

    cudaFuncSetAttribute(gemm_hmma_kernel,
                         cudaFuncAttributeMaxDynamicSharedMemorySize, SMEM_GEMM);
    {
        float* cur;
        cudaGetSymbolAddress((void**)&cur, g_cur);
        dim3 grid((unsigned)(M / 128), OUT / 128);
        gemm_hmma_kernel<<<grid, 256, SMEM_GEMM>>>(x, bias, cur);
    }

    scan_s1_kernel<<<(unsigned)(B * NCH), OUT>>>(decay, T, NCH);
    scan_s2_kernel<<<(unsigned)B, OUT>>>(decay, T, NCH);
    scan_s3_kernel<<<(unsigned)(B * NCH), OUT>>>(decay, T, NCH,
                                                 outputs, statesV, statesZ);
    scan_s4_kernel<<<(unsigned)B, OUT>>>(decay, outputs, statesV, statesZ, T);
}

// round 12
// speedup vs baseline: 1.5871x; 1.0151x over previous
#include <cuda_runtime.h>
#include <cuda_bf16.h>
#include <cstdint>

// ---------------------------------------------------------------------------
// LIF layer forward (sm_103 base ISA):
//   cur = x @ W^T + bias   (3-pass split-bf16 HMMA GEMM; A split fused in-kernel,
//                           B via ldmatrix.x4, 3-stage cp.async pipeline)
//   scan: v = d*v*(1-z) + (1-d)*(cur_t + z @ R^T);  z = (v >= 1)
// Scan chunk-parallelized on the no-spike linear path + exact sequential
// fallback per batch element if any v >= THR (flagged).
// d_out = [outputs | statesV | statesZ]
// ---------------------------------------------------------------------------

#define IN_DIM  512
#define OUT_DIM 512
#define MAX_M   64000
#define MAX_B   128
#define CH      125
#define MAX_NCH 16

__device__ __nv_bfloat16 g_whi[(size_t)OUT_DIM * IN_DIM];
__device__ __nv_bfloat16 g_wlo[(size_t)OUT_DIM * IN_DIM];
__device__ float         g_RT [(size_t)OUT_DIM * OUT_DIM];
__device__ float         g_cur[(size_t)MAX_M * OUT_DIM];
__device__ float         g_csum  [(size_t)MAX_B * MAX_NCH * OUT_DIM];
__device__ float         g_vbound[(size_t)MAX_B * MAX_NCH * OUT_DIM];
__device__ int           g_flag[MAX_B];

// ======================= small prep kernels =================================
__global__ void convert_w_kernel(const float* __restrict__ w) {
    int i = blockIdx.x * blockDim.x + threadIdx.x;
    float4 v = ((const float4*)w)[i];
    float vv[4] = {v.x, v.y, v.z, v.w};
    __nv_bfloat16 h[4], l[4];
#pragma unroll
    for (int k = 0; k < 4; k++) {
        h[k] = __float2bfloat16_rn(vv[k]);
        l[k] = __float2bfloat16_rn(vv[k] - __bfloat162float(h[k]));
    }
    __nv_bfloat162* hi2 = (__nv_bfloat162*)g_whi;
    __nv_bfloat162* lo2 = (__nv_bfloat162*)g_wlo;
    hi2[i * 2]     = __halves2bfloat162(h[0], h[1]);
    hi2[i * 2 + 1] = __halves2bfloat162(h[2], h[3]);
    lo2[i * 2]     = __halves2bfloat162(l[0], l[1]);
    lo2[i * 2 + 1] = __halves2bfloat162(l[2], l[3]);
}

__global__ void transpose512_kernel(const float* __restrict__ R) {
    __shared__ float tile[32][33];
    int x = blockIdx.x * 32 + threadIdx.x;
    int y = blockIdx.y * 32 + threadIdx.y;
    tile[threadIdx.y][threadIdx.x] = R[y * OUT_DIM + x];
    __syncthreads();
    int xo = blockIdx.y * 32 + threadIdx.x;
    int yo = blockIdx.x * 32 + threadIdx.y;
    g_RT[yo * OUT_DIM + xo] = tile[threadIdx.x][threadIdx.y];
}

// ======================= HMMA GEMM ==========================================
// CTA 128x128, BK=64 (8 k-stages), 3-stage cp.async pipeline.
// A staged fp32 (register hi/lo split); B staged bf16 hi/lo, ldmatrix feeds.
#define A_STRIDE_F 68
#define A_PART_B   (128 * A_STRIDE_F * 4)       // 34816
#define B_STRIDE   72
#define B_ROW_B    (B_STRIDE * 2)               // 144
#define B_PART_B   (128 * B_ROW_B)              // 18432
#define STAGE_B    (A_PART_B + 2 * B_PART_B)    // 71680
#define NPIPE      3
#define SMEM_GEMM  (NPIPE * STAGE_B)            // 215040

__device__ __forceinline__ uint32_t smem_u32(const void* p) {
    uint32_t a;
    asm("{ .reg .u64 t; cvta.to.shared.u64 t, %1; cvt.u32.u64 %0, t; }"
        : "=r"(a) : "l"(p));
    return a;
}

__device__ __forceinline__ void cp16(void* dst, const void* src) {
    uint32_t d;
    asm("{ .reg .u64 t; cvta.to.shared.u64 t, %1; cvt.u32.u64 %0, t; }"
        : "=r"(d) : "l"(dst));
    asm volatile("cp.async.cg.shared.global [%0], [%1], 16;" :: "r"(d), "l"(src));
}

__device__ __forceinline__ void ldsm_x4(uint32_t* r, uint32_t addr) {
    asm volatile("ldmatrix.sync.aligned.m8n8.x4.shared.b16 {%0,%1,%2,%3}, [%4];"
        : "=r"(r[0]), "=r"(r[1]), "=r"(r[2]), "=r"(r[3]) : "r"(addr));
}

__device__ __forceinline__ void mma_bf16(float* d, const uint32_t* a,
                                         uint32_t b0, uint32_t b1) {
    asm volatile(
        "mma.sync.aligned.m16n8k16.row.col.f32.bf16.bf16.f32 "
        "{%0,%1,%2,%3}, {%4,%5,%6,%7}, {%8,%9}, {%0,%1,%2,%3};"
        : "+f"(d[0]), "+f"(d[1]), "+f"(d[2]), "+f"(d[3])
        : "r"(a[0]), "r"(a[1]), "r"(a[2]), "r"(a[3]), "r"(b0), "r"(b1));
}

// split two fp32 into (hi bf16x2, lo bf16x2); element 0 in low half.
__device__ __forceinline__ void split2(float2 f, uint32_t& h, uint32_t& l) {
    asm("cvt.rn.bf16x2.f32 %0, %1, %2;" : "=r"(h) : "f"(f.y), "f"(f.x));
    float h0 = __uint_as_float(h << 16);
    float h1 = __uint_as_float(h & 0xffff0000u);
    float l0 = f.x - h0;
    float l1 = f.y - h1;
    asm("cvt.rn.bf16x2.f32 %0, %1, %2;" : "=r"(l) : "f"(l1), "f"(l0));
}

__device__ __forceinline__ void load_stage(char* sm, int buf,
        const float* A, const __nv_bfloat16* Bh, const __nv_bfloat16* Bl,
        int k0, int tid) {
    char* base = sm + buf * STAGE_B;
    {
        const float* gp = A + k0;
#pragma unroll
        for (int it = 0; it < 8; it++) {
            int chunk = it * 256 + tid;
            int row = chunk >> 4;
            int cc  = chunk & 15;
            cp16(base + row * (A_STRIDE_F * 4) + cc * 16,
                 gp + (size_t)row * IN_DIM + cc * 4);
        }
    }
    const __nv_bfloat16* srcs[2] = {Bh, Bl};
#pragma unroll
    for (int p = 0; p < 2; p++) {
        char* pb = base + A_PART_B + p * B_PART_B;
        const __nv_bfloat16* gp = srcs[p] + k0;
#pragma unroll
        for (int it = 0; it < 4; it++) {
            int chunk = it * 256 + tid;
            int row = chunk >> 3;
            int cc  = chunk & 7;
            cp16(pb + row * B_ROW_B + cc * 16,
                 gp + (size_t)row * IN_DIM + cc * 8);
        }
    }
    asm volatile("cp.async.commit_group;");
}

__global__ __launch_bounds__(256)
void gemm_hmma_kernel(const float* __restrict__ x,
                      const float* __restrict__ bias,
                      float* __restrict__ C) {
    extern __shared__ char sm[];
    const uint32_t sbase = smem_u32(sm);
    const int tid  = threadIdx.x;
    const int wid  = tid >> 5;
    const int lane = tid & 31;
    const int g = lane >> 2, t = lane & 3;
    const int wm = wid >> 1;
    const int wn = wid & 1;
    const int m0 = blockIdx.x * 128;
    const int n0 = blockIdx.y * 128;

    const float*         A  = x     + (size_t)m0 * IN_DIM;
    const __nv_bfloat16* Bh = g_whi + (size_t)n0 * IN_DIM;
    const __nv_bfloat16* Bl = g_wlo + (size_t)n0 * IN_DIM;

    const uint32_t bRowOff = (uint32_t)(wn * 64 + (lane & 15)) * B_ROW_B
                           + (uint32_t)(lane >> 4) * 16;

    float d[2][8][4];
#pragma unroll
    for (int mi = 0; mi < 2; mi++)
#pragma unroll
        for (int nj = 0; nj < 8; nj++)
#pragma unroll
            for (int r = 0; r < 4; r++) d[mi][nj][r] = 0.f;

    // 3-stage pipeline: prologue loads stages 0 and 1.
    load_stage(sm, 0, A, Bh, Bl, 0, tid);
    load_stage(sm, 1, A, Bh, Bl, 64, tid);

#pragma unroll 1
    for (int s = 0; s < 8; s++) {
        if (s < 7) {
            asm volatile("cp.async.wait_group 1;");   // stage s arrived
        } else {
            asm volatile("cp.async.wait_group 0;");
        }
        __syncthreads();   // also: all warps done computing stage s-1

        // issue stage s+2 into buffer (s+2)%3 (freed by barrier above)
        if (s + 2 < 8)
            load_stage(sm, (s + 2) % NPIPE, A, Bh, Bl, (s + 2) * 64, tid);

        const int buf = s % NPIPE;
        const float* Af = (const float*)(sm + buf * STAGE_B);
        const uint32_t bHb = sbase + buf * STAGE_B + A_PART_B + bRowOff;
        const uint32_t bLb = bHb + B_PART_B;

#pragma unroll
        for (int kk = 0; kk < 4; kk++) {
            const int col = kk * 16 + 2 * t;
            uint32_t ah[2][4], al[2][4];
#pragma unroll
            for (int mi = 0; mi < 2; mi++) {
                int r0 = wm * 32 + mi * 16 + g;
                float2 f0 = *(const float2*)&Af[(size_t)r0 * A_STRIDE_F + col];
                float2 f1 = *(const float2*)&Af[(size_t)(r0 + 8) * A_STRIDE_F + col];
                float2 f2 = *(const float2*)&Af[(size_t)r0 * A_STRIDE_F + col + 8];
                float2 f3 = *(const float2*)&Af[(size_t)(r0 + 8) * A_STRIDE_F + col + 8];
                split2(f0, ah[mi][0], al[mi][0]);
                split2(f1, ah[mi][1], al[mi][1]);
                split2(f2, ah[mi][2], al[mi][2]);
                split2(f3, ah[mi][3], al[mi][3]);
            }
            uint32_t bh[8][2], bl[8][2];
#pragma unroll
            for (int p = 0; p < 4; p++) {
                uint32_t r[4];
                ldsm_x4(r, bHb + p * (16 * B_ROW_B) + kk * 32);
                bh[2 * p][0] = r[0]; bh[2 * p + 1][0] = r[1];
                bh[2 * p][1] = r[2]; bh[2 * p + 1][1] = r[3];
                ldsm_x4(r, bLb + p * (16 * B_ROW_B) + kk * 32);
                bl[2 * p][0] = r[0]; bl[2 * p + 1][0] = r[1];
                bl[2 * p][1] = r[2]; bl[2 * p + 1][1] = r[3];
            }
#pragma unroll
            for (int mi = 0; mi < 2; mi++)
#pragma unroll
                for (int nj = 0; nj < 8; nj++)
                    mma_bf16(d[mi][nj], ah[mi], bh[nj][0], bh[nj][1]);
#pragma unroll
            for (int mi = 0; mi < 2; mi++)
#pragma unroll
                for (int nj = 0; nj < 8; nj++)
                    mma_bf16(d[mi][nj], ah[mi], bl[nj][0], bl[nj][1]);
#pragma unroll
            for (int mi = 0; mi < 2; mi++)
#pragma unroll
                for (int nj = 0; nj < 8; nj++)
                    mma_bf16(d[mi][nj], al[mi], bh[nj][0], bh[nj][1]);
        }
    }

    // Epilogue: streaming float2 stores + bias (g_cur consumed much later)
#pragma unroll
    for (int nj = 0; nj < 8; nj++) {
        int cc = n0 + wn * 64 + nj * 8 + 2 * t;
        float2 bv = *(const float2*)&bias[cc];
#pragma unroll
        for (int mi = 0; mi < 2; mi++) {
            int r0 = m0 + wm * 32 + mi * 16 + g;
            float2 o0 = {d[mi][nj][0] + bv.x, d[mi][nj][1] + bv.y};
            float2 o1 = {d[mi][nj][2] + bv.x, d[mi][nj][3] + bv.y};
            __stcs((float2*)&C[(size_t)r0 * OUT_DIM + cc], o0);
            __stcs((float2*)&C[(size_t)(r0 + 8) * OUT_DIM + cc], o1);
        }
    }
}

// ================= Parallel scan, stage 1: chunk-local EMA sums ==============
__global__ __launch_bounds__(OUT_DIM)
void scan_s1_kernel(const float* __restrict__ decay, int T, int NCH) {
    const int bc = blockIdx.x;
    const int b  = bc / NCH;
    const int ch = bc % NCH;
    const int o  = threadIdx.x;
    if (ch == 0 && o == 0) g_flag[b] = 0;

    const float d = decay[o];
    const float omd = 1.f - d;
    const int t0 = ch * CH;
    const int len = min(T - t0, CH);
    const float* curB = g_cur + ((size_t)b * T + t0) * OUT_DIM + o;

    float c0 = 0.f, c1 = 0.f, c2 = 0.f, c3 = 0.f;
    if (len > 0) c0 = __ldcs(curB);
    if (len > 1) c1 = __ldcs(curB + (size_t)OUT_DIM);
    if (len > 2) c2 = __ldcs(curB + (size_t)2 * OUT_DIM);
    if (len > 3) c3 = __ldcs(curB + (size_t)3 * OUT_DIM);

    float s = 0.f;
    int t = 0;
#pragma unroll 1
    for (; t + 4 <= len; t += 4) {
        float n0 = (t + 4 < len) ? __ldcs(curB + (size_t)(t + 4) * OUT_DIM) : 0.f;
        float n1 = (t + 5 < len) ? __ldcs(curB + (size_t)(t + 5) * OUT_DIM) : 0.f;
        float n2 = (t + 6 < len) ? __ldcs(curB + (size_t)(t + 6) * OUT_DIM) : 0.f;
        float n3 = (t + 7 < len) ? __ldcs(curB + (size_t)(t + 7) * OUT_DIM) : 0.f;
        s = d * s + omd * c0;
        s = d * s + omd * c1;
        s = d * s + omd * c2;
        s = d * s + omd * c3;
        c0 = n0; c1 = n1; c2 = n2; c3 = n3;
    }
    if (t < len) { s = d * s + omd * c0; t++; }
    if (t < len) { s = d * s + omd * c1; t++; }
    if (t < len) { s = d * s + omd * c2; t++; }

    g_csum[(size_t)bc * OUT_DIM + o] = s;
}

// ================= stage 2: combine chunk boundaries ========================
__global__ __launch_bounds__(OUT_DIM)
void scan_s2_kernel(const float* __restrict__ decay, int T, int NCH) {
    const int b = blockIdx.x;
    const int o = threadIdx.x;
    const float d = decay[o];

    float dpCH = 1.f;
#pragma unroll 1
    for (int i = 0; i < CH; i++) dpCH *= d;

    float vb = 0.f;
#pragma unroll 1
    for (int ch = 0; ch < NCH; ch++) {
        g_vbound[((size_t)b * NCH + ch) * OUT_DIM + o] = vb;
        int len = min(CH, T - ch * CH);
        float dp = dpCH;
        if (len != CH) { dp = 1.f; for (int i = 0; i < len; i++) dp *= d; }
        vb = dp * vb + g_csum[((size_t)b * NCH + ch) * OUT_DIM + o];
    }
}

// ================= stage 3: expand no-spike trajectory + flag ================
__global__ __launch_bounds__(OUT_DIM)
void scan_s3_kernel(const float* __restrict__ decay, int T, int NCH,
                    float* __restrict__ outputs,
                    float* __restrict__ statesV,
                    float* __restrict__ statesZ) {
    const int bc = blockIdx.x;
    const int b  = bc / NCH;
    const int ch = bc % NCH;
    const int o  = threadIdx.x;

    const float d = decay[o];
    const float omd = 1.f - d;
    const int t0 = ch * CH;
    const int len = min(T - t0, CH);

    const float* curB = g_cur + ((size_t)b * T + t0) * OUT_DIM + o;
    float* outB = outputs + ((size_t)b * T + t0) * OUT_DIM + o;
    float* svB  = statesV + ((size_t)b * (T + 1) + t0 + 1) * OUT_DIM + o;
    float* szB  = statesZ + ((size_t)b * (T + 1) + t0 + 1) * OUT_DIM + o;

    if (ch == 0) {
        statesV[((size_t)b * (T + 1)) * OUT_DIM + o] = 0.f;
        statesZ[((size_t)b * (T + 1)) * OUT_DIM + o] = 0.f;
    }

    float c0 = 0.f, c1 = 0.f, c2 = 0.f, c3 = 0.f;
    if (len > 0) c0 = __ldcs(curB);
    if (len > 1) c1 = __ldcs(curB + (size_t)OUT_DIM);
    if (len > 2) c2 = __ldcs(curB + (size_t)2 * OUT_DIM);
    if (len > 3) c3 = __ldcs(curB + (size_t)3 * OUT_DIM);

    float v = g_vbound[(size_t)bc * OUT_DIM + o];
    bool spike = false;
    int t = 0;
#pragma unroll 1
    for (; t + 4 <= len; t += 4) {
        float n0 = (t + 4 < len) ? __ldcs(curB + (size_t)(t + 4) * OUT_DIM) : 0.f;
        float n1 = (t + 5 < len) ? __ldcs(curB + (size_t)(t + 5) * OUT_DIM) : 0.f;
        float n2 = (t + 6 < len) ? __ldcs(curB + (size_t)(t + 6) * OUT_DIM) : 0.f;
        float n3 = (t + 7 < len) ? __ldcs(curB + (size_t)(t + 7) * OUT_DIM) : 0.f;
#pragma unroll
        for (int u = 0; u < 4; u++) {
            float cc = (u == 0) ? c0 : (u == 1) ? c1 : (u == 2) ? c2 : c3;
            v = d * v + omd * cc;
            float z = (v >= 1.f) ? 1.f : 0.f;
            spike |= (z > 0.f);
            size_t off = (size_t)(t + u) * OUT_DIM;
            __stcs(outB + off, z);
            __stcs(svB + off, v);
            __stcs(szB + off, z);
        }
        c0 = n0; c1 = n1; c2 = n2; c3 = n3;
    }
#pragma unroll 1
    for (int u = 0; t < len; t++, u++) {
        float cc = (u == 0) ? c0 : (u == 1) ? c1 : c2;
        v = d * v + omd * cc;
        float z = (v >= 1.f) ? 1.f : 0.f;
        spike |= (z > 0.f);
        size_t off = (size_t)t * OUT_DIM;
        __stcs(outB + off, z);
        __stcs(svB + off, v);
        __stcs(szB + off, z);
    }
    if (__syncthreads_or(spike)) {
        if (o == 0) atomicOr(&g_flag[b], 1);
    }
}

// ================= stage 4: exact sequential fallback (flagged only) ========
__device__ __forceinline__ void lif_step(
    float c, float& v, float& z, int& anySpike,
    unsigned* smask, int o, int wid, int lane,
    float d, float omd,
    float* __restrict__ outB, float* __restrict__ svB, float* __restrict__ szB,
    int t)
{
    float soma = c;
    if (anySpike) {
#pragma unroll 1
        for (int w = 0; w < OUT_DIM / 32; w++) {
            unsigned m = smask[w];
            while (m) {
                int j = w * 32 + (__ffs(m) - 1);
                m &= (m - 1);
                soma += g_RT[(size_t)j * OUT_DIM + o];
            }
        }
    }
    v = d * (v * (1.f - z)) + omd * soma;
    z = (v >= 1.f) ? 1.f : 0.f;
    outB[(size_t)t * OUT_DIM + o]      = z;
    svB[(size_t)(t + 1) * OUT_DIM + o] = v;
    szB[(size_t)(t + 1) * OUT_DIM + o] = z;
    unsigned bal = __ballot_sync(0xffffffffu, z > 0.f);
    anySpike = __syncthreads_count(z > 0.f);
    if (anySpike) {
        if (lane == 0) smask[wid] = bal;
        __syncthreads();
    }
}

__global__ __launch_bounds__(OUT_DIM, 1)
void scan_s4_kernel(const float* __restrict__ decay,
                    float* __restrict__ outputs,
                    float* __restrict__ statesV,
                    float* __restrict__ statesZ,
                    int T) {
    const int b = blockIdx.x;
    if (g_flag[b] == 0) return;
    const int o = threadIdx.x;
    const int wid = o >> 5, lane = o & 31;

    __shared__ unsigned smask[OUT_DIM / 32];
    if (o < OUT_DIM / 32) smask[o] = 0u;

    const float d   = decay[o];
    const float omd = 1.f - d;

    const float* curB = g_cur + (size_t)b * T * OUT_DIM;
    float* outB = outputs + (size_t)b * T * OUT_DIM;
    float* svB  = statesV + (size_t)b * (T + 1) * OUT_DIM;
    float* szB  = statesZ + (size_t)b * (T + 1) * OUT_DIM;

    svB[o] = 0.f;
    szB[o] = 0.f;

    float v = 0.f, z = 0.f;
    int anySpike = 0;
    __syncthreads();

    float c0 = 0.f, c1 = 0.f, c2 = 0.f, c3 = 0.f;
    if (T > 0) c0 = curB[o];
    if (T > 1) c1 = curB[(size_t)OUT_DIM + o];
    if (T > 2) c2 = curB[(size_t)2 * OUT_DIM + o];
    if (T > 3) c3 = curB[(size_t)3 * OUT_DIM + o];

    int t = 0;
#pragma unroll 1
    for (; t + 3 < T; t += 4) {
        float n0 = (t + 4 < T) ? curB[(size_t)(t + 4) * OUT_DIM + o] : 0.f;
        lif_step(c0, v, z, anySpike, smask, o, wid, lane, d, omd, outB, svB, szB, t);
        float n1 = (t + 5 < T) ? curB[(size_t)(t + 5) * OUT_DIM + o] : 0.f;
        lif_step(c1, v, z, anySpike, smask, o, wid, lane, d, omd, outB, svB, szB, t + 1);
        float n2 = (t + 6 < T) ? curB[(size_t)(t + 6) * OUT_DIM + o] : 0.f;
        lif_step(c2, v, z, anySpike, smask, o, wid, lane, d, omd, outB, svB, szB, t + 2);
        float n3 = (t + 7 < T) ? curB[(size_t)(t + 7) * OUT_DIM + o] : 0.f;
        lif_step(c3, v, z, anySpike, smask, o, wid, lane, d, omd, outB, svB, szB, t + 3);
        c0 = n0; c1 = n1; c2 = n2; c3 = n3;
    }
    if (t < T) { lif_step(c0, v, z, anySpike, smask, o, wid, lane, d, omd, outB, svB, szB, t); t++; }
    if (t < T) { lif_step(c1, v, z, anySpike, smask, o, wid, lane, d, omd, outB, svB, szB, t); t++; }
    if (t < T) { lif_step(c2, v, z, anySpike, smask, o, wid, lane, d, omd, outB, svB, szB, t); t++; }
}

// ---------------------------------------------------------------------------
extern "C" void kernel_launch(void* const* d_in, const int* in_sizes, int n_in,
                              void* d_out, int out_size) {
    const float* x      = (const float*)d_in[0];  // [B, T, IN]
    const float* weight = (const float*)d_in[1];  // [OUT, IN]
    const float* bias   = (const float*)d_in[2];  // [OUT]
    const float* recur  = (const float*)d_in[3];  // [OUT, OUT]
    const float* decay  = (const float*)d_in[4];  // [OUT]

    const int OUT = in_sizes[2];                         // 512
    const int IN  = in_sizes[1] / OUT;                   // 512
    const long long M = (long long)in_sizes[0] / IN;     // B*T
    const long long B = (((long long)out_size / OUT) - 3 * M) / 2;
    const int T = (int)(M / B);
    const int NCH = (T + CH - 1) / CH;

    float* outputs = (float*)d_out;                        // [B,T,OUT]
    float* statesV = outputs + (size_t)B * T * OUT;        // [B,T+1,OUT]
    float* statesZ = statesV + (size_t)B * (T + 1) * OUT;  // [B,T+1,OUT]

    convert_w_kernel<<<(OUT * IN / 4) / 256, 256>>>(weight);

    {
        dim3 grid(OUT / 32, OUT / 32), block(32, 32);
        transpose512_kernel<<<grid, block>>>(recur);
    }

    cudaFuncSetAttribute(gemm_hmma_kernel,
                         cudaFuncAttributeMaxDynamicSharedMemorySize, SMEM_GEMM);
    {
        float* cur;
        cudaGetSymbolAddress((void**)&cur, g_cur);
        dim3 grid((unsigned)(M / 128), OUT / 128);
        gemm_hmma_kernel<<<grid, 256, SMEM_GEMM>>>(x, bias, cur);
    }

    scan_s1_kernel<<<(unsigned)(B * NCH), OUT>>>(decay, T, NCH);
    scan_s2_kernel<<<(unsigned)B, OUT>>>(decay, T, NCH);
    scan_s3_kernel<<<(unsigned)(B * NCH), OUT>>>(decay, T, NCH,
                                                 outputs, statesV, statesZ);
    scan_s4_kernel<<<(unsigned)B, OUT>>>(decay, outputs, statesV, statesZ, T);
}